// round 1
// baseline (speedup 1.0000x reference)
#include <cuda_runtime.h>
#include <math.h>

#define BB 2
#define TT 2048
#define DD 1024
#define SS 32
#define CC 128
#define NCH 16

#define ALPHA 0.05f
#define DEC 0.95f
#define RSCL 0.03125f
#define LNEPS 1e-5f

// scratch (device globals; allocation-free per harness rules)
static __device__ float g_hn[BB*TT*DD];
static __device__ float g_q [BB*TT*DD];
static __device__ float g_v [BB*TT*DD];
static __device__ float g_w [BB*TT*SS];
static __device__ float g_U [BB*NCH*SS*DD];
static __device__ float g_Sc[BB*NCH*SS*DD];

// ---------------- K1: LayerNorm ----------------
__global__ void __launch_bounds__(256) k_ln(const float* __restrict__ h,
                                            const float* __restrict__ gamma,
                                            const float* __restrict__ beta) {
    int row = blockIdx.x;
    int tid = threadIdx.x;
    const float4* hp = reinterpret_cast<const float4*>(h) + (size_t)row*(DD/4);
    float4 x = hp[tid];
    float s  = x.x + x.y + x.z + x.w;
    float ss = x.x*x.x + x.y*x.y + x.z*x.z + x.w*x.w;
    #pragma unroll
    for (int o = 16; o > 0; o >>= 1) {
        s  += __shfl_down_sync(0xffffffffu, s, o);
        ss += __shfl_down_sync(0xffffffffu, ss, o);
    }
    __shared__ float rs[8], rss[8];
    if ((tid & 31) == 0) { rs[tid>>5] = s; rss[tid>>5] = ss; }
    __syncthreads();
    if (tid == 0) {
        float a = 0.f, b2 = 0.f;
        #pragma unroll
        for (int i = 0; i < 8; i++) { a += rs[i]; b2 += rss[i]; }
        rs[0] = a; rss[0] = b2;
    }
    __syncthreads();
    float mu   = rs[0] * (1.0f/DD);
    float var  = rss[0] * (1.0f/DD) - mu*mu;
    float rstd = rsqrtf(var + LNEPS);
    float4 g  = reinterpret_cast<const float4*>(gamma)[tid];
    float4 bt = reinterpret_cast<const float4*>(beta)[tid];
    float4 o4;
    o4.x = (x.x - mu)*rstd*g.x + bt.x;
    o4.y = (x.y - mu)*rstd*g.y + bt.y;
    o4.z = (x.z - mu)*rstd*g.z + bt.z;
    o4.w = (x.w - mu)*rstd*g.w + bt.w;
    reinterpret_cast<float4*>(g_hn)[(size_t)row*(DD/4) + tid] = o4;
}

// ---------------- K2: projections q = hn@Wq^T+bq, v = hn@Wv^T+bv ----------------
// NT sgemm, 128x128x16 tile, 256 threads, 8x8 micro-tile.
__global__ void __launch_bounds__(256) k_proj(const float* __restrict__ Wq,
                                              const float* __restrict__ bq,
                                              const float* __restrict__ Wv,
                                              const float* __restrict__ bv) {
    const float* W    = blockIdx.z ? Wv : Wq;
    const float* bias = blockIdx.z ? bv : bq;
    float* O          = blockIdx.z ? g_v : g_q;
    const float* A = g_hn;

    __shared__ float As[16][132];
    __shared__ float Bs[16][132];

    int tid = threadIdx.x;
    int m0 = blockIdx.y * 128;
    int n0 = blockIdx.x * 128;
    int lm = tid >> 2;           // 0..63
    int lk = (tid & 3) * 4;      // 0,4,8,12
    int tm = (tid >> 4) << 3;    // 0..120
    int tn = (tid & 15) << 3;    // 0..120

    float acc[8][8];
    #pragma unroll
    for (int i = 0; i < 8; i++)
        #pragma unroll
        for (int j = 0; j < 8; j++) acc[i][j] = 0.f;

    for (int k0 = 0; k0 < DD; k0 += 16) {
        float4 a0 = *reinterpret_cast<const float4*>(&A[(size_t)(m0+lm   )*DD + k0 + lk]);
        float4 a1 = *reinterpret_cast<const float4*>(&A[(size_t)(m0+lm+64)*DD + k0 + lk]);
        float4 w0 = *reinterpret_cast<const float4*>(&W[(size_t)(n0+lm   )*DD + k0 + lk]);
        float4 w1 = *reinterpret_cast<const float4*>(&W[(size_t)(n0+lm+64)*DD + k0 + lk]);
        As[lk+0][lm]    = a0.x; As[lk+1][lm]    = a0.y; As[lk+2][lm]    = a0.z; As[lk+3][lm]    = a0.w;
        As[lk+0][lm+64] = a1.x; As[lk+1][lm+64] = a1.y; As[lk+2][lm+64] = a1.z; As[lk+3][lm+64] = a1.w;
        Bs[lk+0][lm]    = w0.x; Bs[lk+1][lm]    = w0.y; Bs[lk+2][lm]    = w0.z; Bs[lk+3][lm]    = w0.w;
        Bs[lk+0][lm+64] = w1.x; Bs[lk+1][lm+64] = w1.y; Bs[lk+2][lm+64] = w1.z; Bs[lk+3][lm+64] = w1.w;
        __syncthreads();
        #pragma unroll
        for (int k = 0; k < 16; k++) {
            float4 av0 = *reinterpret_cast<const float4*>(&As[k][tm]);
            float4 av1 = *reinterpret_cast<const float4*>(&As[k][tm+4]);
            float4 bv0 = *reinterpret_cast<const float4*>(&Bs[k][tn]);
            float4 bv1 = *reinterpret_cast<const float4*>(&Bs[k][tn+4]);
            float ar[8] = {av0.x,av0.y,av0.z,av0.w,av1.x,av1.y,av1.z,av1.w};
            float br[8] = {bv0.x,bv0.y,bv0.z,bv0.w,bv1.x,bv1.y,bv1.z,bv1.w};
            #pragma unroll
            for (int i = 0; i < 8; i++)
                #pragma unroll
                for (int j = 0; j < 8; j++) acc[i][j] += ar[i]*br[j];
        }
        __syncthreads();
    }

    float bb[8];
    #pragma unroll
    for (int j = 0; j < 8; j++) bb[j] = bias[n0 + tn + j];
    #pragma unroll
    for (int i = 0; i < 8; i++) {
        float4 o0, o1;
        o0.x = acc[i][0]+bb[0]; o0.y = acc[i][1]+bb[1]; o0.z = acc[i][2]+bb[2]; o0.w = acc[i][3]+bb[3];
        o1.x = acc[i][4]+bb[4]; o1.y = acc[i][5]+bb[5]; o1.z = acc[i][6]+bb[6]; o1.w = acc[i][7]+bb[7];
        size_t ro = (size_t)(m0+tm+i)*DD + n0 + tn;
        *reinterpret_cast<float4*>(&O[ro])   = o0;
        *reinterpret_cast<float4*>(&O[ro+4]) = o1;
    }
}

// ---------------- K3: routing weights w = softmax(q @ state0^T * scale) ----------------
// one block = 64 tokens of one batch
__global__ void __launch_bounds__(256) k_score(const float* __restrict__ state0) {
    int tid = threadIdx.x;
    int m0 = blockIdx.x * 64;          // global token row over B*T
    int b  = m0 / TT;
    const float* q  = g_q + (size_t)m0 * DD;
    const float* st = state0 + (size_t)b * SS * DD;

    __shared__ float As[16][68];
    __shared__ float Bs[16][36];
    __shared__ float sb[64][33];

    int lm = tid >> 2;
    int lk = (tid & 3) * 4;
    int tm = (tid >> 3) * 2;     // 0..62
    int tn = (tid & 7) * 4;      // 0..28

    float acc[2][4] = {{0,0,0,0},{0,0,0,0}};

    for (int k0 = 0; k0 < DD; k0 += 16) {
        float4 a0 = *reinterpret_cast<const float4*>(&q[(size_t)lm*DD + k0 + lk]);
        As[lk+0][lm] = a0.x; As[lk+1][lm] = a0.y; As[lk+2][lm] = a0.z; As[lk+3][lm] = a0.w;
        if (tid < 128) {
            int bn = tid >> 2;
            float4 s0 = *reinterpret_cast<const float4*>(&st[(size_t)bn*DD + k0 + lk]);
            Bs[lk+0][bn] = s0.x; Bs[lk+1][bn] = s0.y; Bs[lk+2][bn] = s0.z; Bs[lk+3][bn] = s0.w;
        }
        __syncthreads();
        #pragma unroll
        for (int k = 0; k < 16; k++) {
            float a_0 = As[k][tm], a_1 = As[k][tm+1];
            #pragma unroll
            for (int j = 0; j < 4; j++) {
                float bvv = Bs[k][tn+j];
                acc[0][j] += a_0*bvv;
                acc[1][j] += a_1*bvv;
            }
        }
        __syncthreads();
    }
    #pragma unroll
    for (int i = 0; i < 2; i++)
        #pragma unroll
        for (int j = 0; j < 4; j++) sb[tm+i][tn+j] = acc[i][j]*RSCL;
    __syncthreads();

    if (tid < 64) {
        float mx = -1e30f;
        for (int ssl = 0; ssl < SS; ssl++) mx = fmaxf(mx, sb[tid][ssl]);
        float sum = 0.f;
        for (int ssl = 0; ssl < SS; ssl++) { float e = expf(sb[tid][ssl]-mx); sb[tid][ssl] = e; sum += e; }
        float inv = 1.f/sum;
        for (int ssl = 0; ssl < SS; ssl++)
            g_w[(size_t)(m0+tid)*SS + ssl] = sb[tid][ssl]*inv;
    }
}

// ---------------- K4: chunk update U_c = alpha * sum_j a^(C-1-j) w_j (x) v_j ----------------
__global__ void __launch_bounds__(256) k_accum() {
    int tid = threadIdx.x;
    int bc = blockIdx.y;
    int b = bc / NCH, c = bc % NCH;
    int d0 = blockIdx.x * 128;

    __shared__ float ws[CC][33];
    __shared__ float vt[16][132];
    __shared__ float pw[CC];

    if (tid < CC) pw[tid] = ALPHA * powf(DEC, (float)(CC-1-tid));
    __syncthreads();
    for (int f = tid; f < CC*SS; f += 256) {
        int j = f >> 5, s = f & 31;
        ws[j][s] = pw[j] * g_w[(size_t)(b*TT + c*CC + j)*SS + s];
    }
    __syncthreads();

    int sg = tid >> 5;       // 0..7
    int dl = tid & 31;       // 0..31
    float acc[4][4];
    #pragma unroll
    for (int i = 0; i < 4; i++)
        #pragma unroll
        for (int j = 0; j < 4; j++) acc[i][j] = 0.f;

    for (int k0 = 0; k0 < CC; k0 += 16) {
        #pragma unroll
        for (int p = 0; p < 2; p++) {
            int f = tid + p*256;
            int row = f >> 5, dq = f & 31;
            float4 v4 = *reinterpret_cast<const float4*>(&g_v[(size_t)(b*TT + c*CC + k0+row)*DD + d0 + dq*4]);
            *reinterpret_cast<float4*>(&vt[row][dq*4]) = v4;
        }
        __syncthreads();
        #pragma unroll
        for (int k = 0; k < 16; k++) {
            float wv[4];
            #pragma unroll
            for (int i = 0; i < 4; i++) wv[i] = ws[k0+k][sg*4+i];
            float4 xv = *reinterpret_cast<const float4*>(&vt[k][dl*4]);
            #pragma unroll
            for (int i = 0; i < 4; i++) {
                acc[i][0] += wv[i]*xv.x; acc[i][1] += wv[i]*xv.y;
                acc[i][2] += wv[i]*xv.z; acc[i][3] += wv[i]*xv.w;
            }
        }
        __syncthreads();
    }
    #pragma unroll
    for (int i = 0; i < 4; i++) {
        float4 o4; o4.x = acc[i][0]; o4.y = acc[i][1]; o4.z = acc[i][2]; o4.w = acc[i][3];
        *reinterpret_cast<float4*>(&g_U[(size_t)((b*NCH + c)*SS + sg*4+i)*DD + d0 + dl*4]) = o4;
    }
}

// ---------------- K5: tiny elementwise scan over chunks + final_state ----------------
__global__ void __launch_bounds__(256) k_scan(const float* __restrict__ state0,
                                              float* __restrict__ out) {
    int gid = blockIdx.x * blockDim.x + threadIdx.x;   // B*S*D threads
    int b = gid / (SS*DD);
    int e = gid % (SS*DD);
    float s = state0[gid];
    float aC = powf(DEC, (float)CC);
    #pragma unroll
    for (int c = 0; c < NCH; c++) {
        size_t off = (size_t)(b*NCH + c)*SS*DD + e;
        g_Sc[off] = s;
        s = aC*s + g_U[off];
    }
    out[(size_t)BB*TT*DD + gid] = s;
}

// ---------------- K6: read phase (per 32-token subtile of a chunk) ----------------
__global__ void __launch_bounds__(256) k_read(float* __restrict__ out) {
    int tid = threadIdx.x;
    int bc = blockIdx.x;
    int b = bc / NCH, c = bc % NCH;
    int t0 = blockIdx.y * 32;
    int tc = c * CC;

    __shared__ float powa[132];
    __shared__ float R1[4224];        // qs[16][36]+xs[16][164] | ws[128][33] | Xs[32][132]
    __shared__ float EsCs[5280];      // Es[160][33] then Cs[32][161]
    __shared__ float sc[32][33];

    float (*qs)[36]  = reinterpret_cast<float(*)[36]>(R1);
    float (*xs)[164] = reinterpret_cast<float(*)[164]>(R1 + 16*36);
    float (*ws)[33]  = reinterpret_cast<float(*)[33]>(R1);
    float (*Xs)[132] = reinterpret_cast<float(*)[132]>(R1);
    float (*Es)[33]  = reinterpret_cast<float(*)[33]>(EsCs);
    float (*Cs)[161] = reinterpret_cast<float(*)[161]>(EsCs);

    if (tid < 130) powa[tid] = powf(DEC, (float)tid);

    const float* Scp = g_Sc + (size_t)(b*NCH + c)*SS*DD;
    const float* qp  = g_q  + (size_t)(b*TT + tc + t0)*DD;
    const float* vp  = g_v  + (size_t)(b*TT + tc)*DD;

    int tg = tid >> 5;       // 0..7
    int lane = tid & 31;

    // ---- stage 1: E[n][t] = q[t] . X[n],  X = [S_c rows (32) ; v chunk (128)] ----
    float acc[4][5];
    #pragma unroll
    for (int i = 0; i < 4; i++)
        #pragma unroll
        for (int jn = 0; jn < 5; jn++) acc[i][jn] = 0.f;

    for (int k0 = 0; k0 < DD; k0 += 16) {
        if (tid < 128) {
            int r = tid >> 2, kq = (tid & 3)*4;
            float4 v4 = *reinterpret_cast<const float4*>(&qp[(size_t)r*DD + k0 + kq]);
            qs[kq+0][r] = v4.x; qs[kq+1][r] = v4.y; qs[kq+2][r] = v4.z; qs[kq+3][r] = v4.w;
        }
        for (int f = tid; f < 640; f += 256) {
            int n = f >> 2, kq = (f & 3)*4;
            const float* src = (n < SS) ? &Scp[(size_t)n*DD + k0 + kq]
                                        : &vp[(size_t)(n-SS)*DD + k0 + kq];
            float4 v4 = *reinterpret_cast<const float4*>(src);
            xs[kq+0][n] = v4.x; xs[kq+1][n] = v4.y; xs[kq+2][n] = v4.z; xs[kq+3][n] = v4.w;
        }
        __syncthreads();
        #pragma unroll
        for (int k = 0; k < 16; k++) {
            float rq[4];
            #pragma unroll
            for (int i = 0; i < 4; i++) rq[i] = qs[k][tg*4+i];
            #pragma unroll
            for (int jn = 0; jn < 5; jn++) {
                float rx = xs[k][lane + 32*jn];
                #pragma unroll
                for (int i = 0; i < 4; i++) acc[i][jn] += rq[i]*rx;
            }
        }
        __syncthreads();
    }
    #pragma unroll
    for (int i = 0; i < 4; i++)
        #pragma unroll
        for (int jn = 0; jn < 5; jn++)
            Es[lane + 32*jn][tg*4+i] = acc[i][jn];
    __syncthreads();

    // load raw w chunk (overwrites qs/xs region; Es is separate)
    for (int f = tid; f < CC*SS; f += 256) {
        int j = f >> 5, s = f & 31;
        ws[j][s] = g_w[(size_t)(b*TT + tc + j)*SS + s];
    }
    __syncthreads();

    // ---- stage 2: scores + softmax over slots ----
    {
        int t = tid >> 3;            // 0..31
        int s4 = (tid & 7)*4;
        int tl = t0 + t;
        float tmp[4] = {0,0,0,0};
        for (int j = 0; j <= tl; j++) {
            float p = Es[SS + j][t] * powa[tl - j];
            tmp[0] += p*ws[j][s4+0];
            tmp[1] += p*ws[j][s4+1];
            tmp[2] += p*ws[j][s4+2];
            tmp[3] += p*ws[j][s4+3];
        }
        float dec1 = powa[tl+1];
        #pragma unroll
        for (int i = 0; i < 4; i++)
            sc[t][s4+i] = RSCL * (dec1 * Es[s4+i][t] + ALPHA * tmp[i]);
    }
    __syncthreads();
    if (tid < 32) {
        float mx = -1e30f;
        for (int s = 0; s < SS; s++) mx = fmaxf(mx, sc[tid][s]);
        float sum = 0.f;
        for (int s = 0; s < SS; s++) { float e = expf(sc[tid][s]-mx); sc[tid][s] = e; sum += e; }
        float inv = 1.f/sum;
        for (int s = 0; s < SS; s++) sc[tid][s] *= inv;
    }
    __syncthreads();

    // ---- stage 3: coefficient matrix Cs[t][0:160] (overwrites Es) ----
    {
        int t = tid >> 3, s4 = (tid & 7)*4;
        float dec1 = powa[t0 + t + 1];
        #pragma unroll
        for (int i = 0; i < 4; i++) Cs[t][s4+i] = dec1 * sc[t][s4+i];
    }
    {
        int tq = tid >> 5;           // 0..7 -> t = tq*4+i
        float bacc[4][4];
        #pragma unroll
        for (int i = 0; i < 4; i++)
            #pragma unroll
            for (int jj = 0; jj < 4; jj++) bacc[i][jj] = 0.f;
        for (int s = 0; s < SS; s++) {
            float at[4];
            #pragma unroll
            for (int i = 0; i < 4; i++) at[i] = sc[tq*4+i][s];
            #pragma unroll
            for (int jj = 0; jj < 4; jj++) {
                float wv = ws[lane + 32*jj][s];
                #pragma unroll
                for (int i = 0; i < 4; i++) bacc[i][jj] += at[i]*wv;
            }
        }
        #pragma unroll
        for (int i = 0; i < 4; i++)
            #pragma unroll
            for (int jj = 0; jj < 4; jj++) {
                int t = tq*4+i, j = lane + 32*jj, tl = t0 + t;
                Cs[t][SS + j] = (j <= tl) ? ALPHA * powa[tl - j] * bacc[i][jj] : 0.f;
            }
    }
    __syncthreads();

    // ---- stage 4: ctx = Cs @ [S_c ; V]  (32 x 1024) ----
    for (int dt = 0; dt < 8; dt++) {
        int d0 = dt*128;
        float4 acc4[4];
        #pragma unroll
        for (int i = 0; i < 4; i++) { acc4[i].x = 0.f; acc4[i].y = 0.f; acc4[i].z = 0.f; acc4[i].w = 0.f; }
        for (int nt = 0; nt < 5; nt++) {
            int n0 = nt*32;
            __syncthreads();
            #pragma unroll
            for (int p = 0; p < 4; p++) {
                int f = tid + p*256;
                int r = f >> 5, dq = f & 31;
                int n = n0 + r;
                const float* src = (n < SS) ? &Scp[(size_t)n*DD + d0 + dq*4]
                                            : &vp[(size_t)(n-SS)*DD + d0 + dq*4];
                *reinterpret_cast<float4*>(&Xs[r][dq*4]) = *reinterpret_cast<const float4*>(src);
            }
            __syncthreads();
            #pragma unroll
            for (int k = 0; k < 32; k++) {
                float cv[4];
                #pragma unroll
                for (int i = 0; i < 4; i++) cv[i] = Cs[tg*4+i][n0+k];
                float4 xv = *reinterpret_cast<const float4*>(&Xs[k][lane*4]);
                #pragma unroll
                for (int i = 0; i < 4; i++) {
                    acc4[i].x += cv[i]*xv.x; acc4[i].y += cv[i]*xv.y;
                    acc4[i].z += cv[i]*xv.z; acc4[i].w += cv[i]*xv.w;
                }
            }
        }
        #pragma unroll
        for (int i = 0; i < 4; i++) {
            size_t ro = (size_t)(b*TT + tc + t0 + tg*4 + i)*DD + d0 + lane*4;
            *reinterpret_cast<float4*>(&out[ro]) = acc4[i];
        }
    }
}

extern "C" void kernel_launch(void* const* d_in, const int* in_sizes, int n_in,
                              void* d_out, int out_size) {
    (void)in_sizes; (void)n_in; (void)out_size;
    const float* h      = (const float*)d_in[0];
    const float* state0 = (const float*)d_in[1];
    const float* gamma  = (const float*)d_in[2];
    const float* beta   = (const float*)d_in[3];
    const float* Wq     = (const float*)d_in[4];
    const float* bq     = (const float*)d_in[5];
    const float* Wv     = (const float*)d_in[6];
    const float* bv     = (const float*)d_in[7];
    float* out = (float*)d_out;

    k_ln<<<BB*TT, 256>>>(h, gamma, beta);

    dim3 gp(DD/128, (BB*TT)/128, 2);
    k_proj<<<gp, 256>>>(Wq, bq, Wv, bv);

    k_score<<<(BB*TT)/64, 256>>>(state0);

    dim3 gu(DD/128, BB*NCH);
    k_accum<<<gu, 256>>>();

    k_scan<<<(BB*SS*DD)/256, 256>>>(state0, out);

    dim3 gr(BB*NCH, CC/32);
    k_read<<<gr, 256>>>(out);
}

// round 10
// speedup vs baseline: 1.5170x; 1.5170x over previous
#include <cuda_runtime.h>
#include <cuda_bf16.h>
#include <math.h>
#include <stdint.h>

#define BB 2
#define TT 2048
#define DD 1024
#define SS 32
#define CC 128
#define NCH 16

#define ALPHA 0.05f
#define DEC 0.95f
#define RSCL 0.03125f
#define LNEPS 1e-5f

// scratch (device globals; allocation-free per harness rules)
static __device__ float g_hn[BB*TT*DD];
static __device__ float g_q [BB*TT*DD];
static __device__ float g_v [BB*TT*DD];
static __device__ float g_w [BB*TT*SS];
static __device__ float g_U [BB*NCH*SS*DD];
static __device__ float g_Sc[BB*NCH*SS*DD];

__device__ __forceinline__ uint32_t smem_u32(const void* p) {
    uint32_t a;
    asm("{ .reg .u64 t; cvta.to.shared.u64 t, %1; cvt.u32.u64 %0, t; }" : "=r"(a) : "l"(p));
    return a;
}

// ---------------- K1: LayerNorm ----------------
__global__ void __launch_bounds__(256) k_ln(const float* __restrict__ h,
                                            const float* __restrict__ gamma,
                                            const float* __restrict__ beta) {
    int row = blockIdx.x;
    int tid = threadIdx.x;
    const float4* hp = reinterpret_cast<const float4*>(h) + (size_t)row*(DD/4);
    float4 x = hp[tid];
    float s  = x.x + x.y + x.z + x.w;
    float ss = x.x*x.x + x.y*x.y + x.z*x.z + x.w*x.w;
    #pragma unroll
    for (int o = 16; o > 0; o >>= 1) {
        s  += __shfl_down_sync(0xffffffffu, s, o);
        ss += __shfl_down_sync(0xffffffffu, ss, o);
    }
    __shared__ float rs[8], rss[8];
    if ((tid & 31) == 0) { rs[tid>>5] = s; rss[tid>>5] = ss; }
    __syncthreads();
    if (tid == 0) {
        float a = 0.f, b2 = 0.f;
        #pragma unroll
        for (int i = 0; i < 8; i++) { a += rs[i]; b2 += rss[i]; }
        rs[0] = a; rss[0] = b2;
    }
    __syncthreads();
    float mu   = rs[0] * (1.0f/DD);
    float var  = rss[0] * (1.0f/DD) - mu*mu;
    float rstd = rsqrtf(var + LNEPS);
    float4 g  = reinterpret_cast<const float4*>(gamma)[tid];
    float4 bt = reinterpret_cast<const float4*>(beta)[tid];
    float4 o4;
    o4.x = (x.x - mu)*rstd*g.x + bt.x;
    o4.y = (x.y - mu)*rstd*g.y + bt.y;
    o4.z = (x.z - mu)*rstd*g.z + bt.z;
    o4.w = (x.w - mu)*rstd*g.w + bt.w;
    reinterpret_cast<float4*>(g_hn)[(size_t)row*(DD/4) + tid] = o4;
}

// ---------------- K2: projections via mma.sync bf16 (3-term hi/lo split) ----------------
// CTA tile 128x128, 8 warps, warp tile 32x64, K-chunk 32, double-buffered SMEM.
// SMEM tile layout: 128 rows x 32 bf16, row stride 80 B (conflict-free ldmatrix).
#define KCH 32
#define ROWB 80
#define TILE_B (128*ROWB)          // 10240
#define STAGE_B (4*TILE_B)         // Ah, Al, Bh, Bl = 40960
#define PROJ_SMEM (2*STAGE_B)      // 81920

__device__ __forceinline__ void ldsm_x4(uint32_t* r, uint32_t addr) {
    asm volatile("ldmatrix.sync.aligned.m8n8.x4.shared.b16 {%0,%1,%2,%3}, [%4];"
                 : "=r"(r[0]), "=r"(r[1]), "=r"(r[2]), "=r"(r[3]) : "r"(addr));
}
__device__ __forceinline__ void mma_bf16(float* d, const uint32_t* a, uint32_t b0, uint32_t b1) {
    asm volatile("mma.sync.aligned.m16n8k16.row.col.f32.bf16.bf16.f32 "
                 "{%0,%1,%2,%3}, {%4,%5,%6,%7}, {%8,%9}, {%0,%1,%2,%3};"
                 : "+f"(d[0]), "+f"(d[1]), "+f"(d[2]), "+f"(d[3])
                 : "r"(a[0]), "r"(a[1]), "r"(a[2]), "r"(a[3]), "r"(b0), "r"(b1));
}
__device__ __forceinline__ void cvt_hilo(float4 x, uint2& hi, uint2& lo) {
    __nv_bfloat162 h01 = __floats2bfloat162_rn(x.x, x.y);
    __nv_bfloat162 h23 = __floats2bfloat162_rn(x.z, x.w);
    float2 f01 = __bfloat1622float2(h01);
    float2 f23 = __bfloat1622float2(h23);
    __nv_bfloat162 l01 = __floats2bfloat162_rn(x.x - f01.x, x.y - f01.y);
    __nv_bfloat162 l23 = __floats2bfloat162_rn(x.z - f23.x, x.w - f23.y);
    hi.x = *reinterpret_cast<uint32_t*>(&h01); hi.y = *reinterpret_cast<uint32_t*>(&h23);
    lo.x = *reinterpret_cast<uint32_t*>(&l01); lo.y = *reinterpret_cast<uint32_t*>(&l23);
}

__global__ void __launch_bounds__(256) k_proj_mma(const float* __restrict__ Wq,
                                                  const float* __restrict__ bq,
                                                  const float* __restrict__ Wv,
                                                  const float* __restrict__ bv) {
    extern __shared__ char smem[];
    const float* W    = blockIdx.z ? Wv : Wq;
    const float* bias = blockIdx.z ? bv : bq;
    float* O          = blockIdx.z ? g_v : g_q;
    int m0 = blockIdx.y * 128;
    int n0 = blockIdx.x * 128;
    int tid = threadIdx.x, wid = tid >> 5, lane = tid & 31;
    int wm = wid & 3, wn = wid >> 2;          // warp tile: rows wm*32, cols wn*64
    uint32_t sb = smem_u32(smem);

    const float* Ap = g_hn + (size_t)m0 * DD;
    const float* Bp = W    + (size_t)n0 * DD;

    float d[2][8][4];
    #pragma unroll
    for (int mi = 0; mi < 2; mi++)
        #pragma unroll
        for (int ni = 0; ni < 8; ni++)
            #pragma unroll
            for (int e = 0; e < 4; e++) d[mi][ni][e] = 0.f;

    int g  = lane >> 3;
    int r8 = lane & 7;

    float4 ra[4], rb[4];
    // prologue: load + stage chunk 0
    #pragma unroll
    for (int i = 0; i < 4; i++) {
        int idx = tid + i*256, row = idx >> 3, c4 = idx & 7;
        ra[i] = *reinterpret_cast<const float4*>(Ap + (size_t)row*DD + c4*4);
        rb[i] = *reinterpret_cast<const float4*>(Bp + (size_t)row*DD + c4*4);
    }
    {
        char* base = smem;
        #pragma unroll
        for (int i = 0; i < 4; i++) {
            int idx = tid + i*256, row = idx >> 3, c4 = idx & 7;
            uint2 hi, lo;
            cvt_hilo(ra[i], hi, lo);
            *reinterpret_cast<uint2*>(base +            row*ROWB + c4*8) = hi;
            *reinterpret_cast<uint2*>(base +   TILE_B + row*ROWB + c4*8) = lo;
            cvt_hilo(rb[i], hi, lo);
            *reinterpret_cast<uint2*>(base + 2*TILE_B + row*ROWB + c4*8) = hi;
            *reinterpret_cast<uint2*>(base + 3*TILE_B + row*ROWB + c4*8) = lo;
        }
    }
    __syncthreads();

    for (int c = 0; c < DD/KCH; c++) {
        int s = c & 1;
        // prefetch next chunk into regs (overlaps with mma below)
        if (c + 1 < DD/KCH) {
            int k0n = (c+1) * KCH;
            #pragma unroll
            for (int i = 0; i < 4; i++) {
                int idx = tid + i*256, row = idx >> 3, c4 = idx & 7;
                ra[i] = *reinterpret_cast<const float4*>(Ap + (size_t)row*DD + k0n + c4*4);
                rb[i] = *reinterpret_cast<const float4*>(Bp + (size_t)row*DD + k0n + c4*4);
            }
        }
        // mma on stage s
        uint32_t Ah = sb + s*STAGE_B;
        uint32_t Al = Ah + TILE_B;
        uint32_t Bh = Ah + 2*TILE_B;
        uint32_t Bl = Ah + 3*TILE_B;
        #pragma unroll
        for (int ks = 0; ks < 2; ks++) {
            int k0 = ks*16;
            uint32_t a_h[2][4], a_l[2][4];
            #pragma unroll
            for (int mi = 0; mi < 2; mi++) {
                int row = wm*32 + mi*16 + (g & 1)*8 + r8;
                int kof = (g >> 1)*8;
                ldsm_x4(a_h[mi], Ah + row*ROWB + (k0 + kof)*2);
                ldsm_x4(a_l[mi], Al + row*ROWB + (k0 + kof)*2);
            }
            uint32_t b_h[4][4], b_l[4][4];
            #pragma unroll
            for (int np = 0; np < 4; np++) {
                int row = wn*64 + np*16 + (g >> 1)*8 + r8;
                int kof = (g & 1)*8;
                ldsm_x4(b_h[np], Bh + row*ROWB + (k0 + kof)*2);
                ldsm_x4(b_l[np], Bl + row*ROWB + (k0 + kof)*2);
            }
            #pragma unroll
            for (int mi = 0; mi < 2; mi++)
                #pragma unroll
                for (int ni = 0; ni < 8; ni++) {
                    uint32_t bh0 = b_h[ni>>1][(ni&1)*2], bh1 = b_h[ni>>1][(ni&1)*2+1];
                    uint32_t bl0 = b_l[ni>>1][(ni&1)*2], bl1 = b_l[ni>>1][(ni&1)*2+1];
                    mma_bf16(d[mi][ni], a_h[mi], bh0, bh1);
                    mma_bf16(d[mi][ni], a_h[mi], bl0, bl1);
                    mma_bf16(d[mi][ni], a_l[mi], bh0, bh1);
                }
        }
        __syncthreads();
        if (c + 1 < DD/KCH) {
            char* base = smem + ((c+1)&1)*STAGE_B;
            #pragma unroll
            for (int i = 0; i < 4; i++) {
                int idx = tid + i*256, row = idx >> 3, c4 = idx & 7;
                uint2 hi, lo;
                cvt_hilo(ra[i], hi, lo);
                *reinterpret_cast<uint2*>(base +            row*ROWB + c4*8) = hi;
                *reinterpret_cast<uint2*>(base +   TILE_B + row*ROWB + c4*8) = lo;
                cvt_hilo(rb[i], hi, lo);
                *reinterpret_cast<uint2*>(base + 2*TILE_B + row*ROWB + c4*8) = hi;
                *reinterpret_cast<uint2*>(base + 3*TILE_B + row*ROWB + c4*8) = lo;
            }
            __syncthreads();
        }
    }

    // epilogue: write fragments + bias
    int qr = lane >> 2;          // 0..7
    int qc = (lane & 3) * 2;
    #pragma unroll
    for (int mi = 0; mi < 2; mi++) {
        #pragma unroll
        for (int ni = 0; ni < 8; ni++) {
            int col = n0 + wn*64 + ni*8 + qc;
            float b0 = bias[col], b1 = bias[col+1];
            int row0 = m0 + wm*32 + mi*16 + qr;
            float2 o0; o0.x = d[mi][ni][0] + b0; o0.y = d[mi][ni][1] + b1;
            float2 o1; o1.x = d[mi][ni][2] + b0; o1.y = d[mi][ni][3] + b1;
            *reinterpret_cast<float2*>(O + (size_t)row0*DD + col)     = o0;
            *reinterpret_cast<float2*>(O + (size_t)(row0+8)*DD + col) = o1;
        }
    }
}

// ---------------- K3: routing weights w = softmax(q @ state0^T * scale) ----------------
__global__ void __launch_bounds__(256) k_score(const float* __restrict__ state0) {
    int tid = threadIdx.x;
    int m0 = blockIdx.x * 64;
    int b  = m0 / TT;
    const float* q  = g_q + (size_t)m0 * DD;
    const float* st = state0 + (size_t)b * SS * DD;

    __shared__ float As[16][68];
    __shared__ float Bs[16][36];
    __shared__ float sb[64][33];

    int lm = tid >> 2;
    int lk = (tid & 3) * 4;
    int tm = (tid >> 3) * 2;
    int tn = (tid & 7) * 4;

    float acc[2][4] = {{0,0,0,0},{0,0,0,0}};

    for (int k0 = 0; k0 < DD; k0 += 16) {
        float4 a0 = *reinterpret_cast<const float4*>(&q[(size_t)lm*DD + k0 + lk]);
        As[lk+0][lm] = a0.x; As[lk+1][lm] = a0.y; As[lk+2][lm] = a0.z; As[lk+3][lm] = a0.w;
        if (tid < 128) {
            int bn = tid >> 2;
            float4 s0 = *reinterpret_cast<const float4*>(&st[(size_t)bn*DD + k0 + lk]);
            Bs[lk+0][bn] = s0.x; Bs[lk+1][bn] = s0.y; Bs[lk+2][bn] = s0.z; Bs[lk+3][bn] = s0.w;
        }
        __syncthreads();
        #pragma unroll
        for (int k = 0; k < 16; k++) {
            float a_0 = As[k][tm], a_1 = As[k][tm+1];
            #pragma unroll
            for (int j = 0; j < 4; j++) {
                float bvv = Bs[k][tn+j];
                acc[0][j] += a_0*bvv;
                acc[1][j] += a_1*bvv;
            }
        }
        __syncthreads();
    }
    #pragma unroll
    for (int i = 0; i < 2; i++)
        #pragma unroll
        for (int j = 0; j < 4; j++) sb[tm+i][tn+j] = acc[i][j]*RSCL;
    __syncthreads();

    if (tid < 64) {
        float mx = -1e30f;
        for (int ssl = 0; ssl < SS; ssl++) mx = fmaxf(mx, sb[tid][ssl]);
        float sum = 0.f;
        for (int ssl = 0; ssl < SS; ssl++) { float e = expf(sb[tid][ssl]-mx); sb[tid][ssl] = e; sum += e; }
        float inv = 1.f/sum;
        for (int ssl = 0; ssl < SS; ssl++)
            g_w[(size_t)(m0+tid)*SS + ssl] = sb[tid][ssl]*inv;
    }
}

// ---------------- K4: chunk update U_c ----------------
__global__ void __launch_bounds__(256) k_accum() {
    int tid = threadIdx.x;
    int bc = blockIdx.y;
    int b = bc / NCH, c = bc % NCH;
    int d0 = blockIdx.x * 128;

    __shared__ float ws[CC][33];
    __shared__ float vt[16][132];
    __shared__ float pw[CC];

    if (tid < CC) pw[tid] = ALPHA * powf(DEC, (float)(CC-1-tid));
    __syncthreads();
    for (int f = tid; f < CC*SS; f += 256) {
        int j = f >> 5, s = f & 31;
        ws[j][s] = pw[j] * g_w[(size_t)(b*TT + c*CC + j)*SS + s];
    }
    __syncthreads();

    int sg = tid >> 5;
    int dl = tid & 31;
    float acc[4][4];
    #pragma unroll
    for (int i = 0; i < 4; i++)
        #pragma unroll
        for (int j = 0; j < 4; j++) acc[i][j] = 0.f;

    for (int k0 = 0; k0 < CC; k0 += 16) {
        #pragma unroll
        for (int p = 0; p < 2; p++) {
            int f = tid + p*256;
            int row = f >> 5, dq = f & 31;
            float4 v4 = *reinterpret_cast<const float4*>(&g_v[(size_t)(b*TT + c*CC + k0+row)*DD + d0 + dq*4]);
            *reinterpret_cast<float4*>(&vt[row][dq*4]) = v4;
        }
        __syncthreads();
        #pragma unroll
        for (int k = 0; k < 16; k++) {
            float wv[4];
            #pragma unroll
            for (int i = 0; i < 4; i++) wv[i] = ws[k0+k][sg*4+i];
            float4 xv = *reinterpret_cast<const float4*>(&vt[k][dl*4]);
            #pragma unroll
            for (int i = 0; i < 4; i++) {
                acc[i][0] += wv[i]*xv.x; acc[i][1] += wv[i]*xv.y;
                acc[i][2] += wv[i]*xv.z; acc[i][3] += wv[i]*xv.w;
            }
        }
        __syncthreads();
    }
    #pragma unroll
    for (int i = 0; i < 4; i++) {
        float4 o4; o4.x = acc[i][0]; o4.y = acc[i][1]; o4.z = acc[i][2]; o4.w = acc[i][3];
        *reinterpret_cast<float4*>(&g_U[(size_t)((b*NCH + c)*SS + sg*4+i)*DD + d0 + dl*4]) = o4;
    }
}

// ---------------- K5: scan over chunks + final_state ----------------
__global__ void __launch_bounds__(256) k_scan(const float* __restrict__ state0,
                                              float* __restrict__ out) {
    int gid = blockIdx.x * blockDim.x + threadIdx.x;
    int b = gid / (SS*DD);
    int e = gid % (SS*DD);
    float s = state0[gid];
    float aC = powf(DEC, (float)CC);
    #pragma unroll
    for (int c = 0; c < NCH; c++) {
        size_t off = (size_t)(b*NCH + c)*SS*DD + e;
        g_Sc[off] = s;
        s = aC*s + g_U[off];
    }
    out[(size_t)BB*TT*DD + gid] = s;
}

// ---------------- K6: read phase ----------------
__global__ void __launch_bounds__(256) k_read(float* __restrict__ out) {
    int tid = threadIdx.x;
    int bc = blockIdx.x;
    int b = bc / NCH, c = bc % NCH;
    int t0 = blockIdx.y * 32;
    int tc = c * CC;

    __shared__ float powa[132];
    __shared__ float R1[4224];
    __shared__ float EsCs[5280];
    __shared__ float sc[32][33];

    float (*qs)[36]  = reinterpret_cast<float(*)[36]>(R1);
    float (*xs)[164] = reinterpret_cast<float(*)[164]>(R1 + 16*36);
    float (*ws)[33]  = reinterpret_cast<float(*)[33]>(R1);
    float (*Xs)[132] = reinterpret_cast<float(*)[132]>(R1);
    float (*Es)[33]  = reinterpret_cast<float(*)[33]>(EsCs);
    float (*Cs)[161] = reinterpret_cast<float(*)[161]>(EsCs);

    if (tid < 130) powa[tid] = powf(DEC, (float)tid);

    const float* Scp = g_Sc + (size_t)(b*NCH + c)*SS*DD;
    const float* qp  = g_q  + (size_t)(b*TT + tc + t0)*DD;
    const float* vp  = g_v  + (size_t)(b*TT + tc)*DD;

    int tg = tid >> 5;
    int lane = tid & 31;

    float acc[4][5];
    #pragma unroll
    for (int i = 0; i < 4; i++)
        #pragma unroll
        for (int jn = 0; jn < 5; jn++) acc[i][jn] = 0.f;

    for (int k0 = 0; k0 < DD; k0 += 16) {
        if (tid < 128) {
            int r = tid >> 2, kq = (tid & 3)*4;
            float4 v4 = *reinterpret_cast<const float4*>(&qp[(size_t)r*DD + k0 + kq]);
            qs[kq+0][r] = v4.x; qs[kq+1][r] = v4.y; qs[kq+2][r] = v4.z; qs[kq+3][r] = v4.w;
        }
        for (int f = tid; f < 640; f += 256) {
            int n = f >> 2, kq = (f & 3)*4;
            const float* src = (n < SS) ? &Scp[(size_t)n*DD + k0 + kq]
                                        : &vp[(size_t)(n-SS)*DD + k0 + kq];
            float4 v4 = *reinterpret_cast<const float4*>(src);
            xs[kq+0][n] = v4.x; xs[kq+1][n] = v4.y; xs[kq+2][n] = v4.z; xs[kq+3][n] = v4.w;
        }
        __syncthreads();
        #pragma unroll
        for (int k = 0; k < 16; k++) {
            float rq[4];
            #pragma unroll
            for (int i = 0; i < 4; i++) rq[i] = qs[k][tg*4+i];
            #pragma unroll
            for (int jn = 0; jn < 5; jn++) {
                float rx = xs[k][lane + 32*jn];
                #pragma unroll
                for (int i = 0; i < 4; i++) acc[i][jn] += rq[i]*rx;
            }
        }
        __syncthreads();
    }
    #pragma unroll
    for (int i = 0; i < 4; i++)
        #pragma unroll
        for (int jn = 0; jn < 5; jn++)
            Es[lane + 32*jn][tg*4+i] = acc[i][jn];
    __syncthreads();

    for (int f = tid; f < CC*SS; f += 256) {
        int j = f >> 5, s = f & 31;
        ws[j][s] = g_w[(size_t)(b*TT + tc + j)*SS + s];
    }
    __syncthreads();

    {
        int t = tid >> 3;
        int s4 = (tid & 7)*4;
        int tl = t0 + t;
        float tmp[4] = {0,0,0,0};
        for (int j = 0; j <= tl; j++) {
            float p = Es[SS + j][t] * powa[tl - j];
            tmp[0] += p*ws[j][s4+0];
            tmp[1] += p*ws[j][s4+1];
            tmp[2] += p*ws[j][s4+2];
            tmp[3] += p*ws[j][s4+3];
        }
        float dec1 = powa[tl+1];
        #pragma unroll
        for (int i = 0; i < 4; i++)
            sc[t][s4+i] = RSCL * (dec1 * Es[s4+i][t] + ALPHA * tmp[i]);
    }
    __syncthreads();
    if (tid < 32) {
        float mx = -1e30f;
        for (int s = 0; s < SS; s++) mx = fmaxf(mx, sc[tid][s]);
        float sum = 0.f;
        for (int s = 0; s < SS; s++) { float e = expf(sc[tid][s]-mx); sc[tid][s] = e; sum += e; }
        float inv = 1.f/sum;
        for (int s = 0; s < SS; s++) sc[tid][s] *= inv;
    }
    __syncthreads();

    {
        int t = tid >> 3, s4 = (tid & 7)*4;
        float dec1 = powa[t0 + t + 1];
        #pragma unroll
        for (int i = 0; i < 4; i++) Cs[t][s4+i] = dec1 * sc[t][s4+i];
    }
    {
        int tq = tid >> 5;
        float bacc[4][4];
        #pragma unroll
        for (int i = 0; i < 4; i++)
            #pragma unroll
            for (int jj = 0; jj < 4; jj++) bacc[i][jj] = 0.f;
        for (int s = 0; s < SS; s++) {
            float at[4];
            #pragma unroll
            for (int i = 0; i < 4; i++) at[i] = sc[tq*4+i][s];
            #pragma unroll
            for (int jj = 0; jj < 4; jj++) {
                float wv = ws[lane + 32*jj][s];
                #pragma unroll
                for (int i = 0; i < 4; i++) bacc[i][jj] += at[i]*wv;
            }
        }
        #pragma unroll
        for (int i = 0; i < 4; i++)
            #pragma unroll
            for (int jj = 0; jj < 4; jj++) {
                int t = tq*4+i, j = lane + 32*jj, tl = t0 + t;
                Cs[t][SS + j] = (j <= tl) ? ALPHA * powa[tl - j] * bacc[i][jj] : 0.f;
            }
    }
    __syncthreads();

    for (int dt = 0; dt < 8; dt++) {
        int d0 = dt*128;
        float4 acc4[4];
        #pragma unroll
        for (int i = 0; i < 4; i++) { acc4[i].x = 0.f; acc4[i].y = 0.f; acc4[i].z = 0.f; acc4[i].w = 0.f; }
        for (int nt = 0; nt < 5; nt++) {
            int n0 = nt*32;
            __syncthreads();
            #pragma unroll
            for (int p = 0; p < 4; p++) {
                int f = tid + p*256;
                int r = f >> 5, dq = f & 31;
                int n = n0 + r;
                const float* src = (n < SS) ? &Scp[(size_t)n*DD + d0 + dq*4]
                                            : &vp[(size_t)(n-SS)*DD + d0 + dq*4];
                *reinterpret_cast<float4*>(&Xs[r][dq*4]) = *reinterpret_cast<const float4*>(src);
            }
            __syncthreads();
            #pragma unroll
            for (int k = 0; k < 32; k++) {
                float cv[4];
                #pragma unroll
                for (int i = 0; i < 4; i++) cv[i] = Cs[tg*4+i][n0+k];
                float4 xv = *reinterpret_cast<const float4*>(&Xs[k][lane*4]);
                #pragma unroll
                for (int i = 0; i < 4; i++) {
                    acc4[i].x += cv[i]*xv.x; acc4[i].y += cv[i]*xv.y;
                    acc4[i].z += cv[i]*xv.z; acc4[i].w += cv[i]*xv.w;
                }
            }
        }
        #pragma unroll
        for (int i = 0; i < 4; i++) {
            size_t ro = (size_t)(b*TT + tc + t0 + tg*4 + i)*DD + d0 + lane*4;
            *reinterpret_cast<float4*>(&out[ro]) = acc4[i];
        }
    }
}

extern "C" void kernel_launch(void* const* d_in, const int* in_sizes, int n_in,
                              void* d_out, int out_size) {
    (void)in_sizes; (void)n_in; (void)out_size;
    const float* h      = (const float*)d_in[0];
    const float* state0 = (const float*)d_in[1];
    const float* gamma  = (const float*)d_in[2];
    const float* beta   = (const float*)d_in[3];
    const float* Wq     = (const float*)d_in[4];
    const float* bq     = (const float*)d_in[5];
    const float* Wv     = (const float*)d_in[6];
    const float* bv     = (const float*)d_in[7];
    float* out = (float*)d_out;

    static int configured = 0;
    if (!configured) {
        cudaFuncSetAttribute(k_proj_mma, cudaFuncAttributeMaxDynamicSharedMemorySize, PROJ_SMEM);
        configured = 1;
    }

    k_ln<<<BB*TT, 256>>>(h, gamma, beta);

    dim3 gp(DD/128, (BB*TT)/128, 2);
    k_proj_mma<<<gp, 256, PROJ_SMEM>>>(Wq, bq, Wv, bv);

    k_score<<<(BB*TT)/64, 256>>>(state0);

    dim3 gu(DD/128, BB*NCH);
    k_accum<<<gu, 256>>>();

    k_scan<<<(BB*SS*DD)/256, 256>>>(state0, out);

    dim3 gr(BB*NCH, CC/32);
    k_read<<<gr, 256>>>(out);
}

// round 11
// speedup vs baseline: 1.5603x; 1.0286x over previous
#include <cuda_runtime.h>
#include <cuda_bf16.h>
#include <math.h>
#include <stdint.h>

#define BB 2
#define TT 2048
#define DD 1024
#define SS 32
#define CC 128
#define NCH 16

#define ALPHA 0.05f
#define DEC 0.95f
#define RSCL 0.03125f
#define LNEPS 1e-5f

// scratch (device globals; allocation-free per harness rules)
static __device__ float g_q [BB*TT*DD];
static __device__ float g_v [BB*TT*DD];
static __device__ float g_w [BB*TT*SS];
static __device__ float g_U [BB*NCH*SS*DD];
static __device__ float g_Sc[BB*NCH*SS*DD];
// bf16 hi/lo split operands for tensor-core GEMM
static __device__ __nv_bfloat16 g_ah[BB*TT*DD];
static __device__ __nv_bfloat16 g_al[BB*TT*DD];
static __device__ __nv_bfloat16 g_wh[2*DD*DD];
static __device__ __nv_bfloat16 g_wl[2*DD*DD];

__device__ __forceinline__ uint32_t smem_u32(const void* p) {
    uint32_t a;
    asm("{ .reg .u64 t; cvta.to.shared.u64 t, %1; cvt.u32.u64 %0, t; }" : "=r"(a) : "l"(p));
    return a;
}
__device__ __forceinline__ void cvt_hilo(float4 x, uint2& hi, uint2& lo) {
    __nv_bfloat162 h01 = __floats2bfloat162_rn(x.x, x.y);
    __nv_bfloat162 h23 = __floats2bfloat162_rn(x.z, x.w);
    float2 f01 = __bfloat1622float2(h01);
    float2 f23 = __bfloat1622float2(h23);
    __nv_bfloat162 l01 = __floats2bfloat162_rn(x.x - f01.x, x.y - f01.y);
    __nv_bfloat162 l23 = __floats2bfloat162_rn(x.z - f23.x, x.w - f23.y);
    hi.x = *reinterpret_cast<uint32_t*>(&h01); hi.y = *reinterpret_cast<uint32_t*>(&h23);
    lo.x = *reinterpret_cast<uint32_t*>(&l01); lo.y = *reinterpret_cast<uint32_t*>(&l23);
}

// ---------------- K1: LayerNorm -> bf16 hi/lo ----------------
__global__ void __launch_bounds__(256) k_ln(const float* __restrict__ h,
                                            const float* __restrict__ gamma,
                                            const float* __restrict__ beta) {
    int row = blockIdx.x;
    int tid = threadIdx.x;
    const float4* hp = reinterpret_cast<const float4*>(h) + (size_t)row*(DD/4);
    float4 x = hp[tid];
    float s  = x.x + x.y + x.z + x.w;
    float ss = x.x*x.x + x.y*x.y + x.z*x.z + x.w*x.w;
    #pragma unroll
    for (int o = 16; o > 0; o >>= 1) {
        s  += __shfl_down_sync(0xffffffffu, s, o);
        ss += __shfl_down_sync(0xffffffffu, ss, o);
    }
    __shared__ float rs[8], rss[8];
    if ((tid & 31) == 0) { rs[tid>>5] = s; rss[tid>>5] = ss; }
    __syncthreads();
    if (tid == 0) {
        float a = 0.f, b2 = 0.f;
        #pragma unroll
        for (int i = 0; i < 8; i++) { a += rs[i]; b2 += rss[i]; }
        rs[0] = a; rss[0] = b2;
    }
    __syncthreads();
    float mu   = rs[0] * (1.0f/DD);
    float var  = rss[0] * (1.0f/DD) - mu*mu;
    float rstd = rsqrtf(var + LNEPS);
    float4 g  = reinterpret_cast<const float4*>(gamma)[tid];
    float4 bt = reinterpret_cast<const float4*>(beta)[tid];
    float4 o4;
    o4.x = (x.x - mu)*rstd*g.x + bt.x;
    o4.y = (x.y - mu)*rstd*g.y + bt.y;
    o4.z = (x.z - mu)*rstd*g.z + bt.z;
    o4.w = (x.w - mu)*rstd*g.w + bt.w;
    uint2 hi, lo;
    cvt_hilo(o4, hi, lo);
    reinterpret_cast<uint2*>(g_ah)[(size_t)row*(DD/4) + tid] = hi;
    reinterpret_cast<uint2*>(g_al)[(size_t)row*(DD/4) + tid] = lo;
}

// ---------------- K1b: convert Wq|Wv -> bf16 hi/lo (once) ----------------
__global__ void __launch_bounds__(256) k_cvtw(const float* __restrict__ Wq,
                                              const float* __restrict__ Wv) {
    int idx = blockIdx.x * 256 + threadIdx.x;      // float4 index over 2*DD*DD
    const int half = DD*DD/4;
    const float* src = (idx < half) ? Wq : Wv;
    int loc = (idx < half) ? idx : idx - half;
    float4 x = reinterpret_cast<const float4*>(src)[loc];
    uint2 hi, lo;
    cvt_hilo(x, hi, lo);
    reinterpret_cast<uint2*>(g_wh)[idx] = hi;
    reinterpret_cast<uint2*>(g_wl)[idx] = lo;
}

// ---------------- K2: projections via mma.sync bf16 (3-term), cp.async pipeline ----------------
#define KCH 32
#define ROWB 80
#define TILE_B (128*ROWB)          // 10240
#define STAGE_B (4*TILE_B)         // Ah, Al, Bh, Bl = 40960
#define PROJ_SMEM (2*STAGE_B)      // 81920

__device__ __forceinline__ void ldsm_x4(uint32_t* r, uint32_t addr) {
    asm volatile("ldmatrix.sync.aligned.m8n8.x4.shared.b16 {%0,%1,%2,%3}, [%4];"
                 : "=r"(r[0]), "=r"(r[1]), "=r"(r[2]), "=r"(r[3]) : "r"(addr));
}
__device__ __forceinline__ void mma_bf16(float* d, const uint32_t* a, uint32_t b0, uint32_t b1) {
    asm volatile("mma.sync.aligned.m16n8k16.row.col.f32.bf16.bf16.f32 "
                 "{%0,%1,%2,%3}, {%4,%5,%6,%7}, {%8,%9}, {%0,%1,%2,%3};"
                 : "+f"(d[0]), "+f"(d[1]), "+f"(d[2]), "+f"(d[3])
                 : "r"(a[0]), "r"(a[1]), "r"(a[2]), "r"(a[3]), "r"(b0), "r"(b1));
}
__device__ __forceinline__ void cp16(uint32_t dst, const void* src) {
    asm volatile("cp.async.cg.shared.global [%0], [%1], 16;" :: "r"(dst), "l"(src));
}
#define CP_COMMIT() asm volatile("cp.async.commit_group;" ::: "memory")
#define CP_WAIT1()  asm volatile("cp.async.wait_group 1;" ::: "memory")
#define CP_WAIT0()  asm volatile("cp.async.wait_group 0;" ::: "memory")

__global__ void __launch_bounds__(256) k_proj_mma(const float* __restrict__ bq,
                                                  const float* __restrict__ bv) {
    extern __shared__ char smem[];
    const float* bias = blockIdx.z ? bv : bq;
    float* O          = blockIdx.z ? g_v : g_q;
    int m0 = blockIdx.y * 128;
    int n0 = blockIdx.x * 128;
    int tid = threadIdx.x, wid = tid >> 5, lane = tid & 31;
    int wm = wid & 3, wn = wid >> 2;
    uint32_t sb = smem_u32(smem);

    const __nv_bfloat16* Ah_g = g_ah + (size_t)m0 * DD;
    const __nv_bfloat16* Al_g = g_al + (size_t)m0 * DD;
    const __nv_bfloat16* Bh_g = g_wh + (size_t)blockIdx.z*DD*DD + (size_t)n0 * DD;
    const __nv_bfloat16* Bl_g = g_wl + (size_t)blockIdx.z*DD*DD + (size_t)n0 * DD;

    // issue one stage of copies: 4 tiles x 128 rows x 4 x 16B = 2048 chunks, 8/thread
    auto issue = [&](int stage, int c) {
        int k0 = c * KCH;
        uint32_t dstb = sb + stage*STAGE_B;
        #pragma unroll
        for (int i = 0; i < 8; i++) {
            int idx = tid + i*256;
            int tile = idx >> 9;               // 0..3
            int ch   = idx & 511;
            int row  = ch >> 2;
            int c16  = ch & 3;
            const __nv_bfloat16* src =
                (tile == 0) ? Ah_g : (tile == 1) ? Al_g : (tile == 2) ? Bh_g : Bl_g;
            cp16(dstb + tile*TILE_B + row*ROWB + c16*16,
                 src + (size_t)row*DD + k0 + c16*8);
        }
        CP_COMMIT();
    };

    float d[2][8][4];
    #pragma unroll
    for (int mi = 0; mi < 2; mi++)
        #pragma unroll
        for (int ni = 0; ni < 8; ni++)
            #pragma unroll
            for (int e = 0; e < 4; e++) d[mi][ni][e] = 0.f;

    int g  = lane >> 3;
    int r8 = lane & 7;

    issue(0, 0);
    issue(1, 1);

    for (int c = 0; c < DD/KCH; c++) {
        int s = c & 1;
        if (c + 2 < DD/KCH) CP_WAIT1(); else CP_WAIT0();
        __syncthreads();

        uint32_t Ah = sb + s*STAGE_B;
        uint32_t Al = Ah + TILE_B;
        uint32_t Bh = Ah + 2*TILE_B;
        uint32_t Bl = Ah + 3*TILE_B;
        #pragma unroll
        for (int ks = 0; ks < 2; ks++) {
            int k0 = ks*16;
            uint32_t a_h[2][4], a_l[2][4];
            #pragma unroll
            for (int mi = 0; mi < 2; mi++) {
                int row = wm*32 + mi*16 + (g & 1)*8 + r8;
                int kof = (g >> 1)*8;
                ldsm_x4(a_h[mi], Ah + row*ROWB + (k0 + kof)*2);
                ldsm_x4(a_l[mi], Al + row*ROWB + (k0 + kof)*2);
            }
            uint32_t b_h[4][4], b_l[4][4];
            #pragma unroll
            for (int np = 0; np < 4; np++) {
                int row = wn*64 + np*16 + (g >> 1)*8 + r8;
                int kof = (g & 1)*8;
                ldsm_x4(b_h[np], Bh + row*ROWB + (k0 + kof)*2);
                ldsm_x4(b_l[np], Bl + row*ROWB + (k0 + kof)*2);
            }
            #pragma unroll
            for (int mi = 0; mi < 2; mi++)
                #pragma unroll
                for (int ni = 0; ni < 8; ni++) {
                    uint32_t bh0 = b_h[ni>>1][(ni&1)*2], bh1 = b_h[ni>>1][(ni&1)*2+1];
                    uint32_t bl0 = b_l[ni>>1][(ni&1)*2], bl1 = b_l[ni>>1][(ni&1)*2+1];
                    mma_bf16(d[mi][ni], a_h[mi], bh0, bh1);
                    mma_bf16(d[mi][ni], a_h[mi], bl0, bl1);
                    mma_bf16(d[mi][ni], a_l[mi], bh0, bh1);
                }
        }
        __syncthreads();
        if (c + 2 < DD/KCH) issue(s, c + 2);
    }

    // epilogue: write fragments + bias
    int qr = lane >> 2;
    int qc = (lane & 3) * 2;
    #pragma unroll
    for (int mi = 0; mi < 2; mi++) {
        #pragma unroll
        for (int ni = 0; ni < 8; ni++) {
            int col = n0 + wn*64 + ni*8 + qc;
            float b0 = bias[col], b1 = bias[col+1];
            int row0 = m0 + wm*32 + mi*16 + qr;
            float2 o0; o0.x = d[mi][ni][0] + b0; o0.y = d[mi][ni][1] + b1;
            float2 o1; o1.x = d[mi][ni][2] + b0; o1.y = d[mi][ni][3] + b1;
            *reinterpret_cast<float2*>(O + (size_t)row0*DD + col)     = o0;
            *reinterpret_cast<float2*>(O + (size_t)(row0+8)*DD + col) = o1;
        }
    }
}

// ---------------- K3: routing weights w = softmax(q @ state0^T * scale) ----------------
__global__ void __launch_bounds__(256) k_score(const float* __restrict__ state0) {
    int tid = threadIdx.x;
    int m0 = blockIdx.x * 64;
    int b  = m0 / TT;
    const float* q  = g_q + (size_t)m0 * DD;
    const float* st = state0 + (size_t)b * SS * DD;

    __shared__ float As[16][68];
    __shared__ float Bs[16][36];
    __shared__ float sb[64][33];

    int lm = tid >> 2;
    int lk = (tid & 3) * 4;
    int tm = (tid >> 3) * 2;
    int tn = (tid & 7) * 4;

    float acc[2][4] = {{0,0,0,0},{0,0,0,0}};

    for (int k0 = 0; k0 < DD; k0 += 16) {
        float4 a0 = *reinterpret_cast<const float4*>(&q[(size_t)lm*DD + k0 + lk]);
        As[lk+0][lm] = a0.x; As[lk+1][lm] = a0.y; As[lk+2][lm] = a0.z; As[lk+3][lm] = a0.w;
        if (tid < 128) {
            int bn = tid >> 2;
            float4 s0 = *reinterpret_cast<const float4*>(&st[(size_t)bn*DD + k0 + lk]);
            Bs[lk+0][bn] = s0.x; Bs[lk+1][bn] = s0.y; Bs[lk+2][bn] = s0.z; Bs[lk+3][bn] = s0.w;
        }
        __syncthreads();
        #pragma unroll
        for (int k = 0; k < 16; k++) {
            float a_0 = As[k][tm], a_1 = As[k][tm+1];
            #pragma unroll
            for (int j = 0; j < 4; j++) {
                float bvv = Bs[k][tn+j];
                acc[0][j] += a_0*bvv;
                acc[1][j] += a_1*bvv;
            }
        }
        __syncthreads();
    }
    #pragma unroll
    for (int i = 0; i < 2; i++)
        #pragma unroll
        for (int j = 0; j < 4; j++) sb[tm+i][tn+j] = acc[i][j]*RSCL;
    __syncthreads();

    if (tid < 64) {
        float mx = -1e30f;
        for (int ssl = 0; ssl < SS; ssl++) mx = fmaxf(mx, sb[tid][ssl]);
        float sum = 0.f;
        for (int ssl = 0; ssl < SS; ssl++) { float e = expf(sb[tid][ssl]-mx); sb[tid][ssl] = e; sum += e; }
        float inv = 1.f/sum;
        for (int ssl = 0; ssl < SS; ssl++)
            g_w[(size_t)(m0+tid)*SS + ssl] = sb[tid][ssl]*inv;
    }
}

// ---------------- K4: chunk update U_c ----------------
__global__ void __launch_bounds__(256) k_accum() {
    int tid = threadIdx.x;
    int bc = blockIdx.y;
    int b = bc / NCH, c = bc % NCH;
    int d0 = blockIdx.x * 128;

    __shared__ float ws[CC][33];
    __shared__ float vt[16][132];
    __shared__ float pw[CC];

    if (tid < CC) pw[tid] = ALPHA * powf(DEC, (float)(CC-1-tid));
    __syncthreads();
    for (int f = tid; f < CC*SS; f += 256) {
        int j = f >> 5, s = f & 31;
        ws[j][s] = pw[j] * g_w[(size_t)(b*TT + c*CC + j)*SS + s];
    }
    __syncthreads();

    int sg = tid >> 5;
    int dl = tid & 31;
    float acc[4][4];
    #pragma unroll
    for (int i = 0; i < 4; i++)
        #pragma unroll
        for (int j = 0; j < 4; j++) acc[i][j] = 0.f;

    for (int k0 = 0; k0 < CC; k0 += 16) {
        #pragma unroll
        for (int p = 0; p < 2; p++) {
            int f = tid + p*256;
            int row = f >> 5, dq = f & 31;
            float4 v4 = *reinterpret_cast<const float4*>(&g_v[(size_t)(b*TT + c*CC + k0+row)*DD + d0 + dq*4]);
            *reinterpret_cast<float4*>(&vt[row][dq*4]) = v4;
        }
        __syncthreads();
        #pragma unroll
        for (int k = 0; k < 16; k++) {
            float wv[4];
            #pragma unroll
            for (int i = 0; i < 4; i++) wv[i] = ws[k0+k][sg*4+i];
            float4 xv = *reinterpret_cast<const float4*>(&vt[k][dl*4]);
            #pragma unroll
            for (int i = 0; i < 4; i++) {
                acc[i][0] += wv[i]*xv.x; acc[i][1] += wv[i]*xv.y;
                acc[i][2] += wv[i]*xv.z; acc[i][3] += wv[i]*xv.w;
            }
        }
        __syncthreads();
    }
    #pragma unroll
    for (int i = 0; i < 4; i++) {
        float4 o4; o4.x = acc[i][0]; o4.y = acc[i][1]; o4.z = acc[i][2]; o4.w = acc[i][3];
        *reinterpret_cast<float4*>(&g_U[(size_t)((b*NCH + c)*SS + sg*4+i)*DD + d0 + dl*4]) = o4;
    }
}

// ---------------- K5: scan over chunks + final_state ----------------
__global__ void __launch_bounds__(256) k_scan(const float* __restrict__ state0,
                                              float* __restrict__ out) {
    int gid = blockIdx.x * blockDim.x + threadIdx.x;
    int b = gid / (SS*DD);
    int e = gid % (SS*DD);
    float s = state0[gid];
    float aC = powf(DEC, (float)CC);
    #pragma unroll
    for (int c = 0; c < NCH; c++) {
        size_t off = (size_t)(b*NCH + c)*SS*DD + e;
        g_Sc[off] = s;
        s = aC*s + g_U[off];
    }
    out[(size_t)BB*TT*DD + gid] = s;
}

// ---------------- K6: read phase ----------------
__global__ void __launch_bounds__(256) k_read(float* __restrict__ out) {
    int tid = threadIdx.x;
    int bc = blockIdx.x;
    int b = bc / NCH, c = bc % NCH;
    int t0 = blockIdx.y * 32;
    int tc = c * CC;

    __shared__ float powa[132];
    __shared__ float R1[4224];
    __shared__ float EsCs[5280];
    __shared__ float sc[32][33];

    float (*qs)[36]  = reinterpret_cast<float(*)[36]>(R1);
    float (*xs)[164] = reinterpret_cast<float(*)[164]>(R1 + 16*36);
    float (*ws)[33]  = reinterpret_cast<float(*)[33]>(R1);
    float (*Xs)[132] = reinterpret_cast<float(*)[132]>(R1);
    float (*Es)[33]  = reinterpret_cast<float(*)[33]>(EsCs);
    float (*Cs)[161] = reinterpret_cast<float(*)[161]>(EsCs);

    if (tid < 130) powa[tid] = powf(DEC, (float)tid);

    const float* Scp = g_Sc + (size_t)(b*NCH + c)*SS*DD;
    const float* qp  = g_q  + (size_t)(b*TT + tc + t0)*DD;
    const float* vp  = g_v  + (size_t)(b*TT + tc)*DD;

    int tg = tid >> 5;
    int lane = tid & 31;

    float acc[4][5];
    #pragma unroll
    for (int i = 0; i < 4; i++)
        #pragma unroll
        for (int jn = 0; jn < 5; jn++) acc[i][jn] = 0.f;

    for (int k0 = 0; k0 < DD; k0 += 16) {
        if (tid < 128) {
            int r = tid >> 2, kq = (tid & 3)*4;
            float4 v4 = *reinterpret_cast<const float4*>(&qp[(size_t)r*DD + k0 + kq]);
            qs[kq+0][r] = v4.x; qs[kq+1][r] = v4.y; qs[kq+2][r] = v4.z; qs[kq+3][r] = v4.w;
        }
        for (int f = tid; f < 640; f += 256) {
            int n = f >> 2, kq = (f & 3)*4;
            const float* src = (n < SS) ? &Scp[(size_t)n*DD + k0 + kq]
                                        : &vp[(size_t)(n-SS)*DD + k0 + kq];
            float4 v4 = *reinterpret_cast<const float4*>(src);
            xs[kq+0][n] = v4.x; xs[kq+1][n] = v4.y; xs[kq+2][n] = v4.z; xs[kq+3][n] = v4.w;
        }
        __syncthreads();
        #pragma unroll
        for (int k = 0; k < 16; k++) {
            float rq[4];
            #pragma unroll
            for (int i = 0; i < 4; i++) rq[i] = qs[k][tg*4+i];
            #pragma unroll
            for (int jn = 0; jn < 5; jn++) {
                float rx = xs[k][lane + 32*jn];
                #pragma unroll
                for (int i = 0; i < 4; i++) acc[i][jn] += rq[i]*rx;
            }
        }
        __syncthreads();
    }
    #pragma unroll
    for (int i = 0; i < 4; i++)
        #pragma unroll
        for (int jn = 0; jn < 5; jn++)
            Es[lane + 32*jn][tg*4+i] = acc[i][jn];
    __syncthreads();

    for (int f = tid; f < CC*SS; f += 256) {
        int j = f >> 5, s = f & 31;
        ws[j][s] = g_w[(size_t)(b*TT + tc + j)*SS + s];
    }
    __syncthreads();

    {
        int t = tid >> 3;
        int s4 = (tid & 7)*4;
        int tl = t0 + t;
        float tmp[4] = {0,0,0,0};
        for (int j = 0; j <= tl; j++) {
            float p = Es[SS + j][t] * powa[tl - j];
            tmp[0] += p*ws[j][s4+0];
            tmp[1] += p*ws[j][s4+1];
            tmp[2] += p*ws[j][s4+2];
            tmp[3] += p*ws[j][s4+3];
        }
        float dec1 = powa[tl+1];
        #pragma unroll
        for (int i = 0; i < 4; i++)
            sc[t][s4+i] = RSCL * (dec1 * Es[s4+i][t] + ALPHA * tmp[i]);
    }
    __syncthreads();
    if (tid < 32) {
        float mx = -1e30f;
        for (int s = 0; s < SS; s++) mx = fmaxf(mx, sc[tid][s]);
        float sum = 0.f;
        for (int s = 0; s < SS; s++) { float e = expf(sc[tid][s]-mx); sc[tid][s] = e; sum += e; }
        float inv = 1.f/sum;
        for (int s = 0; s < SS; s++) sc[tid][s] *= inv;
    }
    __syncthreads();

    {
        int t = tid >> 3, s4 = (tid & 7)*4;
        float dec1 = powa[t0 + t + 1];
        #pragma unroll
        for (int i = 0; i < 4; i++) Cs[t][s4+i] = dec1 * sc[t][s4+i];
    }
    {
        int tq = tid >> 5;
        float bacc[4][4];
        #pragma unroll
        for (int i = 0; i < 4; i++)
            #pragma unroll
            for (int jj = 0; jj < 4; jj++) bacc[i][jj] = 0.f;
        for (int s = 0; s < SS; s++) {
            float at[4];
            #pragma unroll
            for (int i = 0; i < 4; i++) at[i] = sc[tq*4+i][s];
            #pragma unroll
            for (int jj = 0; jj < 4; jj++) {
                float wv = ws[lane + 32*jj][s];
                #pragma unroll
                for (int i = 0; i < 4; i++) bacc[i][jj] += at[i]*wv;
            }
        }
        #pragma unroll
        for (int i = 0; i < 4; i++)
            #pragma unroll
            for (int jj = 0; jj < 4; jj++) {
                int t = tq*4+i, j = lane + 32*jj, tl = t0 + t;
                Cs[t][SS + j] = (j <= tl) ? ALPHA * powa[tl - j] * bacc[i][jj] : 0.f;
            }
    }
    __syncthreads();

    for (int dt = 0; dt < 8; dt++) {
        int d0 = dt*128;
        float4 acc4[4];
        #pragma unroll
        for (int i = 0; i < 4; i++) { acc4[i].x = 0.f; acc4[i].y = 0.f; acc4[i].z = 0.f; acc4[i].w = 0.f; }
        for (int nt = 0; nt < 5; nt++) {
            int n0 = nt*32;
            __syncthreads();
            #pragma unroll
            for (int p = 0; p < 4; p++) {
                int f = tid + p*256;
                int r = f >> 5, dq = f & 31;
                int n = n0 + r;
                const float* src = (n < SS) ? &Scp[(size_t)n*DD + d0 + dq*4]
                                            : &vp[(size_t)(n-SS)*DD + d0 + dq*4];
                *reinterpret_cast<float4*>(&Xs[r][dq*4]) = *reinterpret_cast<const float4*>(src);
            }
            __syncthreads();
            #pragma unroll
            for (int k = 0; k < 32; k++) {
                float cv[4];
                #pragma unroll
                for (int i = 0; i < 4; i++) cv[i] = Cs[tg*4+i][n0+k];
                float4 xv = *reinterpret_cast<const float4*>(&Xs[k][lane*4]);
                #pragma unroll
                for (int i = 0; i < 4; i++) {
                    acc4[i].x += cv[i]*xv.x; acc4[i].y += cv[i]*xv.y;
                    acc4[i].z += cv[i]*xv.z; acc4[i].w += cv[i]*xv.w;
                }
            }
        }
        #pragma unroll
        for (int i = 0; i < 4; i++) {
            size_t ro = (size_t)(b*TT + tc + t0 + tg*4 + i)*DD + d0 + lane*4;
            *reinterpret_cast<float4*>(&out[ro]) = acc4[i];
        }
    }
}

extern "C" void kernel_launch(void* const* d_in, const int* in_sizes, int n_in,
                              void* d_out, int out_size) {
    (void)in_sizes; (void)n_in; (void)out_size;
    const float* h      = (const float*)d_in[0];
    const float* state0 = (const float*)d_in[1];
    const float* gamma  = (const float*)d_in[2];
    const float* beta   = (const float*)d_in[3];
    const float* Wq     = (const float*)d_in[4];
    const float* bq     = (const float*)d_in[5];
    const float* Wv     = (const float*)d_in[6];
    const float* bv     = (const float*)d_in[7];
    float* out = (float*)d_out;

    static int configured = 0;
    if (!configured) {
        cudaFuncSetAttribute(k_proj_mma, cudaFuncAttributeMaxDynamicSharedMemorySize, PROJ_SMEM);
        configured = 1;
    }

    k_ln<<<BB*TT, 256>>>(h, gamma, beta);
    k_cvtw<<<(2*DD*DD/4)/256, 256>>>(Wq, Wv);

    dim3 gp(DD/128, (BB*TT)/128, 2);
    k_proj_mma<<<gp, 256, PROJ_SMEM>>>(bq, bv);

    k_score<<<(BB*TT)/64, 256>>>(state0);

    dim3 gu(DD/128, BB*NCH);
    k_accum<<<gu, 256>>>();

    k_scan<<<(BB*SS*DD)/256, 256>>>(state0, out);

    dim3 gr(BB*NCH, CC/32);
    k_read<<<gr, 256>>>(out);
}

// round 13
// speedup vs baseline: 2.0010x; 1.2824x over previous
#include <cuda_runtime.h>
#include <cuda_bf16.h>
#include <math.h>
#include <stdint.h>

#define BB 2
#define TT 2048
#define DD 1024
#define SS 32
#define CC 128
#define NCH 16

#define ALPHA 0.05f
#define DEC 0.95f
#define RSCL 0.03125f
#define LNEPS 1e-5f

// scratch (device globals; allocation-free per harness rules)
static __device__ float g_q [BB*TT*DD];
static __device__ float g_v [BB*TT*DD];
static __device__ float g_w [BB*TT*SS];
static __device__ float g_sp[4*BB*TT*SS];       // k-split score partials
static __device__ float g_U [BB*NCH*SS*DD];
static __device__ float g_Sc[BB*NCH*SS*DD];
// bf16 hi/lo split operands for tensor-core GEMM
static __device__ __nv_bfloat16 g_ah[BB*TT*DD];
static __device__ __nv_bfloat16 g_al[BB*TT*DD];
static __device__ __nv_bfloat16 g_wh[2*DD*DD];
static __device__ __nv_bfloat16 g_wl[2*DD*DD];

__device__ __forceinline__ uint32_t smem_u32(const void* p) {
    uint32_t a;
    asm("{ .reg .u64 t; cvta.to.shared.u64 t, %1; cvt.u32.u64 %0, t; }" : "=r"(a) : "l"(p));
    return a;
}
__device__ __forceinline__ void cvt_hilo(float4 x, uint2& hi, uint2& lo) {
    __nv_bfloat162 h01 = __floats2bfloat162_rn(x.x, x.y);
    __nv_bfloat162 h23 = __floats2bfloat162_rn(x.z, x.w);
    float2 f01 = __bfloat1622float2(h01);
    float2 f23 = __bfloat1622float2(h23);
    __nv_bfloat162 l01 = __floats2bfloat162_rn(x.x - f01.x, x.y - f01.y);
    __nv_bfloat162 l23 = __floats2bfloat162_rn(x.z - f23.x, x.w - f23.y);
    hi.x = *reinterpret_cast<uint32_t*>(&h01); hi.y = *reinterpret_cast<uint32_t*>(&h23);
    lo.x = *reinterpret_cast<uint32_t*>(&l01); lo.y = *reinterpret_cast<uint32_t*>(&l23);
}

// ---------------- K1: LayerNorm -> bf16 hi/lo ----------------
__global__ void __launch_bounds__(256) k_ln(const float* __restrict__ h,
                                            const float* __restrict__ gamma,
                                            const float* __restrict__ beta) {
    int row = blockIdx.x;
    int tid = threadIdx.x;
    const float4* hp = reinterpret_cast<const float4*>(h) + (size_t)row*(DD/4);
    float4 x = hp[tid];
    float s  = x.x + x.y + x.z + x.w;
    float ss = x.x*x.x + x.y*x.y + x.z*x.z + x.w*x.w;
    #pragma unroll
    for (int o = 16; o > 0; o >>= 1) {
        s  += __shfl_down_sync(0xffffffffu, s, o);
        ss += __shfl_down_sync(0xffffffffu, ss, o);
    }
    __shared__ float rs[8], rss[8];
    if ((tid & 31) == 0) { rs[tid>>5] = s; rss[tid>>5] = ss; }
    __syncthreads();
    if (tid == 0) {
        float a = 0.f, b2 = 0.f;
        #pragma unroll
        for (int i = 0; i < 8; i++) { a += rs[i]; b2 += rss[i]; }
        rs[0] = a; rss[0] = b2;
    }
    __syncthreads();
    float mu   = rs[0] * (1.0f/DD);
    float var  = rss[0] * (1.0f/DD) - mu*mu;
    float rstd = rsqrtf(var + LNEPS);
    float4 g  = reinterpret_cast<const float4*>(gamma)[tid];
    float4 bt = reinterpret_cast<const float4*>(beta)[tid];
    float4 o4;
    o4.x = (x.x - mu)*rstd*g.x + bt.x;
    o4.y = (x.y - mu)*rstd*g.y + bt.y;
    o4.z = (x.z - mu)*rstd*g.z + bt.z;
    o4.w = (x.w - mu)*rstd*g.w + bt.w;
    uint2 hi, lo;
    cvt_hilo(o4, hi, lo);
    reinterpret_cast<uint2*>(g_ah)[(size_t)row*(DD/4) + tid] = hi;
    reinterpret_cast<uint2*>(g_al)[(size_t)row*(DD/4) + tid] = lo;
}

// ---------------- K1b: convert Wq|Wv -> bf16 hi/lo (once) ----------------
__global__ void __launch_bounds__(256) k_cvtw(const float* __restrict__ Wq,
                                              const float* __restrict__ Wv) {
    int idx = blockIdx.x * 256 + threadIdx.x;
    const int half = DD*DD/4;
    const float* src = (idx < half) ? Wq : Wv;
    int loc = (idx < half) ? idx : idx - half;
    float4 x = reinterpret_cast<const float4*>(src)[loc];
    uint2 hi, lo;
    cvt_hilo(x, hi, lo);
    reinterpret_cast<uint2*>(g_wh)[idx] = hi;
    reinterpret_cast<uint2*>(g_wl)[idx] = lo;
}

// ---------------- K2: projections via mma.sync bf16 (3-term), cp.async pipeline ----------------
#define KCH 32
#define ROWB 80
#define TILE_B (128*ROWB)
#define STAGE_B (4*TILE_B)
#define PROJ_SMEM (2*STAGE_B)

__device__ __forceinline__ void ldsm_x4(uint32_t* r, uint32_t addr) {
    asm volatile("ldmatrix.sync.aligned.m8n8.x4.shared.b16 {%0,%1,%2,%3}, [%4];"
                 : "=r"(r[0]), "=r"(r[1]), "=r"(r[2]), "=r"(r[3]) : "r"(addr));
}
__device__ __forceinline__ void mma_bf16(float* d, const uint32_t* a, uint32_t b0, uint32_t b1) {
    asm volatile("mma.sync.aligned.m16n8k16.row.col.f32.bf16.bf16.f32 "
                 "{%0,%1,%2,%3}, {%4,%5,%6,%7}, {%8,%9}, {%0,%1,%2,%3};"
                 : "+f"(d[0]), "+f"(d[1]), "+f"(d[2]), "+f"(d[3])
                 : "r"(a[0]), "r"(a[1]), "r"(a[2]), "r"(a[3]), "r"(b0), "r"(b1));
}
__device__ __forceinline__ void cp16(uint32_t dst, const void* src) {
    asm volatile("cp.async.cg.shared.global [%0], [%1], 16;" :: "r"(dst), "l"(src));
}
#define CP_COMMIT() asm volatile("cp.async.commit_group;" ::: "memory")
#define CP_WAIT1()  asm volatile("cp.async.wait_group 1;" ::: "memory")
#define CP_WAIT0()  asm volatile("cp.async.wait_group 0;" ::: "memory")

__global__ void __launch_bounds__(256) k_proj_mma(const float* __restrict__ bq,
                                                  const float* __restrict__ bv) {
    extern __shared__ char smem[];
    const float* bias = blockIdx.z ? bv : bq;
    float* O          = blockIdx.z ? g_v : g_q;
    int m0 = blockIdx.y * 128;
    int n0 = blockIdx.x * 128;
    int tid = threadIdx.x, wid = tid >> 5, lane = tid & 31;
    int wm = wid & 3, wn = wid >> 2;
    uint32_t sb = smem_u32(smem);

    const __nv_bfloat16* Ah_g = g_ah + (size_t)m0 * DD;
    const __nv_bfloat16* Al_g = g_al + (size_t)m0 * DD;
    const __nv_bfloat16* Bh_g = g_wh + (size_t)blockIdx.z*DD*DD + (size_t)n0 * DD;
    const __nv_bfloat16* Bl_g = g_wl + (size_t)blockIdx.z*DD*DD + (size_t)n0 * DD;

    auto issue = [&](int stage, int c) {
        int k0 = c * KCH;
        uint32_t dstb = sb + stage*STAGE_B;
        #pragma unroll
        for (int i = 0; i < 8; i++) {
            int idx = tid + i*256;
            int tile = idx >> 9;
            int ch   = idx & 511;
            int row  = ch >> 2;
            int c16  = ch & 3;
            const __nv_bfloat16* src =
                (tile == 0) ? Ah_g : (tile == 1) ? Al_g : (tile == 2) ? Bh_g : Bl_g;
            cp16(dstb + tile*TILE_B + row*ROWB + c16*16,
                 src + (size_t)row*DD + k0 + c16*8);
        }
        CP_COMMIT();
    };

    float d[2][8][4];
    #pragma unroll
    for (int mi = 0; mi < 2; mi++)
        #pragma unroll
        for (int ni = 0; ni < 8; ni++)
            #pragma unroll
            for (int e = 0; e < 4; e++) d[mi][ni][e] = 0.f;

    int g  = lane >> 3;
    int r8 = lane & 7;

    issue(0, 0);
    issue(1, 1);

    for (int c = 0; c < DD/KCH; c++) {
        int s = c & 1;
        if (c + 2 < DD/KCH) CP_WAIT1(); else CP_WAIT0();
        __syncthreads();

        uint32_t Ah = sb + s*STAGE_B;
        uint32_t Al = Ah + TILE_B;
        uint32_t Bh = Ah + 2*TILE_B;
        uint32_t Bl = Ah + 3*TILE_B;
        #pragma unroll
        for (int ks = 0; ks < 2; ks++) {
            int k0 = ks*16;
            uint32_t a_h[2][4], a_l[2][4];
            #pragma unroll
            for (int mi = 0; mi < 2; mi++) {
                int row = wm*32 + mi*16 + (g & 1)*8 + r8;
                int kof = (g >> 1)*8;
                ldsm_x4(a_h[mi], Ah + row*ROWB + (k0 + kof)*2);
                ldsm_x4(a_l[mi], Al + row*ROWB + (k0 + kof)*2);
            }
            uint32_t b_h[4][4], b_l[4][4];
            #pragma unroll
            for (int np = 0; np < 4; np++) {
                int row = wn*64 + np*16 + (g >> 1)*8 + r8;
                int kof = (g & 1)*8;
                ldsm_x4(b_h[np], Bh + row*ROWB + (k0 + kof)*2);
                ldsm_x4(b_l[np], Bl + row*ROWB + (k0 + kof)*2);
            }
            #pragma unroll
            for (int mi = 0; mi < 2; mi++)
                #pragma unroll
                for (int ni = 0; ni < 8; ni++) {
                    uint32_t bh0 = b_h[ni>>1][(ni&1)*2], bh1 = b_h[ni>>1][(ni&1)*2+1];
                    uint32_t bl0 = b_l[ni>>1][(ni&1)*2], bl1 = b_l[ni>>1][(ni&1)*2+1];
                    mma_bf16(d[mi][ni], a_h[mi], bh0, bh1);
                    mma_bf16(d[mi][ni], a_h[mi], bl0, bl1);
                    mma_bf16(d[mi][ni], a_l[mi], bh0, bh1);
                }
        }
        __syncthreads();
        if (c + 2 < DD/KCH) issue(s, c + 2);
    }

    int qr = lane >> 2;
    int qc = (lane & 3) * 2;
    #pragma unroll
    for (int mi = 0; mi < 2; mi++) {
        #pragma unroll
        for (int ni = 0; ni < 8; ni++) {
            int col = n0 + wn*64 + ni*8 + qc;
            float b0 = bias[col], b1 = bias[col+1];
            int row0 = m0 + wm*32 + mi*16 + qr;
            float2 o0; o0.x = d[mi][ni][0] + b0; o0.y = d[mi][ni][1] + b1;
            float2 o1; o1.x = d[mi][ni][2] + b0; o1.y = d[mi][ni][3] + b1;
            *reinterpret_cast<float2*>(O + (size_t)row0*DD + col)     = o0;
            *reinterpret_cast<float2*>(O + (size_t)(row0+8)*DD + col) = o1;
        }
    }
}

// ---------------- K3a: score partials (k-split x4, double-buffered) ----------------
__global__ void __launch_bounds__(256) k_score1(const float* __restrict__ state0) {
    int tid = threadIdx.x;
    int m0 = blockIdx.x * 64;
    int kp = blockIdx.y;
    int b  = m0 / TT;
    const float* q  = g_q + (size_t)m0 * DD + kp*256;
    const float* st = state0 + (size_t)b * SS * DD + kp*256;

    __shared__ float As[2][32][68];
    __shared__ float Bs[2][32][36];

    float4 ra[2], rb;
    auto fetch = [&](int c) {
        int k0 = c * 32;
        #pragma unroll
        for (int i = 0; i < 2; i++) {
            int idx = tid + i*256, row = idx >> 3, qd = idx & 7;
            ra[i] = *reinterpret_cast<const float4*>(q + (size_t)row*DD + k0 + qd*4);
        }
        { int row = tid >> 3, qd = tid & 7;
          rb = *reinterpret_cast<const float4*>(st + (size_t)row*DD + k0 + qd*4); }
    };
    auto store = [&](int s) {
        #pragma unroll
        for (int i = 0; i < 2; i++) {
            int idx = tid + i*256, row = idx >> 3, qd = idx & 7;
            As[s][qd*4+0][row] = ra[i].x; As[s][qd*4+1][row] = ra[i].y;
            As[s][qd*4+2][row] = ra[i].z; As[s][qd*4+3][row] = ra[i].w;
        }
        { int row = tid >> 3, qd = tid & 7;
          Bs[s][qd*4+0][row] = rb.x; Bs[s][qd*4+1][row] = rb.y;
          Bs[s][qd*4+2][row] = rb.z; Bs[s][qd*4+3][row] = rb.w; }
    };

    int tm = (tid >> 3) * 2;
    int tn = (tid & 7) * 4;
    float acc[2][4] = {{0,0,0,0},{0,0,0,0}};

    fetch(0);
    for (int c = 0; c < 8; c++) {
        int s = c & 1;
        store(s);
        __syncthreads();
        if (c < 7) fetch(c + 1);
        #pragma unroll
        for (int k = 0; k < 32; k++) {
            float a0 = As[s][k][tm], a1 = As[s][k][tm+1];
            #pragma unroll
            for (int j = 0; j < 4; j++) {
                float bv = Bs[s][k][tn+j];
                acc[0][j] += a0*bv;
                acc[1][j] += a1*bv;
            }
        }
        __syncthreads();
    }
    #pragma unroll
    for (int i = 0; i < 2; i++)
        #pragma unroll
        for (int j = 0; j < 4; j++)
            g_sp[((size_t)kp*BB*TT + m0 + tm + i)*SS + tn + j] = acc[i][j];
}

// ---------------- K3b: sum partials + softmax ----------------
__global__ void __launch_bounds__(128) k_softmax() {
    int t = blockIdx.x * 128 + threadIdx.x;       // 0..B*T-1
    float v[SS];
    #pragma unroll
    for (int s4 = 0; s4 < 8; s4++) {
        float4 a = *reinterpret_cast<const float4*>(&g_sp[((size_t)0*BB*TT + t)*SS + s4*4]);
        float4 b = *reinterpret_cast<const float4*>(&g_sp[((size_t)1*BB*TT + t)*SS + s4*4]);
        float4 c = *reinterpret_cast<const float4*>(&g_sp[((size_t)2*BB*TT + t)*SS + s4*4]);
        float4 d = *reinterpret_cast<const float4*>(&g_sp[((size_t)3*BB*TT + t)*SS + s4*4]);
        v[s4*4+0] = (a.x + b.x + c.x + d.x) * RSCL;
        v[s4*4+1] = (a.y + b.y + c.y + d.y) * RSCL;
        v[s4*4+2] = (a.z + b.z + c.z + d.z) * RSCL;
        v[s4*4+3] = (a.w + b.w + c.w + d.w) * RSCL;
    }
    float mx = -1e30f;
    #pragma unroll
    for (int s = 0; s < SS; s++) mx = fmaxf(mx, v[s]);
    float sum = 0.f;
    #pragma unroll
    for (int s = 0; s < SS; s++) { v[s] = expf(v[s]-mx); sum += v[s]; }
    float inv = 1.f/sum;
    #pragma unroll
    for (int s4 = 0; s4 < 8; s4++) {
        float4 o;
        o.x = v[s4*4+0]*inv; o.y = v[s4*4+1]*inv;
        o.z = v[s4*4+2]*inv; o.w = v[s4*4+3]*inv;
        *reinterpret_cast<float4*>(&g_w[(size_t)t*SS + s4*4]) = o;
    }
}

// ---------------- K4: chunk update U_c (double-buffered + prefetch) ----------------
__global__ void __launch_bounds__(256) k_accum() {
    int tid = threadIdx.x;
    int bc = blockIdx.y;
    int b = bc / NCH, c = bc % NCH;
    int d0 = blockIdx.x * 128;

    __shared__ float ws[CC][33];
    __shared__ float vt[2][16][132];
    __shared__ float pw[CC];

    if (tid < CC) pw[tid] = ALPHA * powf(DEC, (float)(CC-1-tid));
    __syncthreads();
    for (int f = tid; f < CC*SS; f += 256) {
        int j = f >> 5, s = f & 31;
        ws[j][s] = pw[j] * g_w[(size_t)(b*TT + c*CC + j)*SS + s];
    }

    int sg = tid >> 5;
    int dl = tid & 31;
    float acc[4][4];
    #pragma unroll
    for (int i = 0; i < 4; i++)
        #pragma unroll
        for (int j = 0; j < 4; j++) acc[i][j] = 0.f;

    float4 rv[2];
    auto fetchv = [&](int cc) {
        int k0 = cc * 16;
        #pragma unroll
        for (int p = 0; p < 2; p++) {
            int f = tid + p*256;
            int row = f >> 5, dq = f & 31;
            rv[p] = *reinterpret_cast<const float4*>(
                &g_v[(size_t)(b*TT + c*CC + k0 + row)*DD + d0 + dq*4]);
        }
    };

    fetchv(0);
    for (int cc = 0; cc < CC/16; cc++) {
        int s = cc & 1;
        #pragma unroll
        for (int p = 0; p < 2; p++) {
            int f = tid + p*256;
            int row = f >> 5, dq = f & 31;
            *reinterpret_cast<float4*>(&vt[s][row][dq*4]) = rv[p];
        }
        __syncthreads();
        if (cc + 1 < CC/16) fetchv(cc + 1);
        int k0 = cc * 16;
        #pragma unroll
        for (int k = 0; k < 16; k++) {
            float wv[4];
            #pragma unroll
            for (int i = 0; i < 4; i++) wv[i] = ws[k0+k][sg*4+i];
            float4 xv = *reinterpret_cast<const float4*>(&vt[s][k][dl*4]);
            #pragma unroll
            for (int i = 0; i < 4; i++) {
                acc[i][0] += wv[i]*xv.x; acc[i][1] += wv[i]*xv.y;
                acc[i][2] += wv[i]*xv.z; acc[i][3] += wv[i]*xv.w;
            }
        }
        __syncthreads();
    }
    #pragma unroll
    for (int i = 0; i < 4; i++) {
        float4 o4; o4.x = acc[i][0]; o4.y = acc[i][1]; o4.z = acc[i][2]; o4.w = acc[i][3];
        *reinterpret_cast<float4*>(&g_U[(size_t)((b*NCH + c)*SS + sg*4+i)*DD + d0 + dl*4]) = o4;
    }
}

// ---------------- K5: scan over chunks + final_state ----------------
__global__ void __launch_bounds__(256) k_scan(const float* __restrict__ state0,
                                              float* __restrict__ out) {
    int gid = blockIdx.x * blockDim.x + threadIdx.x;
    int b = gid / (SS*DD);
    int e = gid % (SS*DD);
    float s = state0[gid];
    float aC = powf(DEC, (float)CC);
    #pragma unroll
    for (int c = 0; c < NCH; c++) {
        size_t off = (size_t)(b*NCH + c)*SS*DD + e;
        g_Sc[off] = s;
        s = aC*s + g_U[off];
    }
    out[(size_t)BB*TT*DD + gid] = s;
}

// ---------------- K6: read phase (with register prefetch) ----------------
__global__ void __launch_bounds__(256) k_read(float* __restrict__ out) {
    int tid = threadIdx.x;
    int bc = blockIdx.x;
    int b = bc / NCH, c = bc % NCH;
    int t0 = blockIdx.y * 32;
    int tc = c * CC;

    __shared__ float powa[132];
    __shared__ float R1[4224];
    __shared__ float EsCs[5280];
    __shared__ float sc[32][33];

    float (*qs)[36]  = reinterpret_cast<float(*)[36]>(R1);
    float (*xs)[164] = reinterpret_cast<float(*)[164]>(R1 + 16*36);
    float (*ws)[33]  = reinterpret_cast<float(*)[33]>(R1);
    float (*Xs)[132] = reinterpret_cast<float(*)[132]>(R1);
    float (*Es)[33]  = reinterpret_cast<float(*)[33]>(EsCs);
    float (*Cs)[161] = reinterpret_cast<float(*)[161]>(EsCs);

    if (tid < 130) powa[tid] = powf(DEC, (float)tid);

    const float* Scp = g_Sc + (size_t)(b*NCH + c)*SS*DD;
    const float* qp  = g_q  + (size_t)(b*TT + tc + t0)*DD;
    const float* vp  = g_v  + (size_t)(b*TT + tc)*DD;

    int tg = tid >> 5;
    int lane = tid & 31;

    // ---- stage 1 with register prefetch ----
    float acc[4][5];
    #pragma unroll
    for (int i = 0; i < 4; i++)
        #pragma unroll
        for (int jn = 0; jn < 5; jn++) acc[i][jn] = 0.f;

    float4 rq, rx[3];
    auto fetch1 = [&](int k0) {
        if (tid < 128) {
            int r = tid >> 2, kq = (tid & 3)*4;
            rq = *reinterpret_cast<const float4*>(&qp[(size_t)r*DD + k0 + kq]);
        }
        #pragma unroll
        for (int p = 0; p < 3; p++) {
            int f = tid + p*256;
            if (f < 640) {
                int n = f >> 2, kq = (f & 3)*4;
                const float* src = (n < SS) ? &Scp[(size_t)n*DD + k0 + kq]
                                            : &vp[(size_t)(n-SS)*DD + k0 + kq];
                rx[p] = *reinterpret_cast<const float4*>(src);
            }
        }
    };

    fetch1(0);
    for (int k0 = 0; k0 < DD; k0 += 16) {
        if (tid < 128) {
            int r = tid >> 2, kq = (tid & 3)*4;
            qs[kq+0][r] = rq.x; qs[kq+1][r] = rq.y; qs[kq+2][r] = rq.z; qs[kq+3][r] = rq.w;
        }
        #pragma unroll
        for (int p = 0; p < 3; p++) {
            int f = tid + p*256;
            if (f < 640) {
                int n = f >> 2, kq = (f & 3)*4;
                xs[kq+0][n] = rx[p].x; xs[kq+1][n] = rx[p].y;
                xs[kq+2][n] = rx[p].z; xs[kq+3][n] = rx[p].w;
            }
        }
        __syncthreads();
        if (k0 + 16 < DD) fetch1(k0 + 16);
        #pragma unroll
        for (int k = 0; k < 16; k++) {
            float rqv[4];
            #pragma unroll
            for (int i = 0; i < 4; i++) rqv[i] = qs[k][tg*4+i];
            #pragma unroll
            for (int jn = 0; jn < 5; jn++) {
                float rxv = xs[k][lane + 32*jn];
                #pragma unroll
                for (int i = 0; i < 4; i++) acc[i][jn] += rqv[i]*rxv;
            }
        }
        __syncthreads();
    }
    #pragma unroll
    for (int i = 0; i < 4; i++)
        #pragma unroll
        for (int jn = 0; jn < 5; jn++)
            Es[lane + 32*jn][tg*4+i] = acc[i][jn];
    __syncthreads();

    for (int f = tid; f < CC*SS; f += 256) {
        int j = f >> 5, s = f & 31;
        ws[j][s] = g_w[(size_t)(b*TT + tc + j)*SS + s];
    }
    __syncthreads();

    // ---- stage 2: scores + softmax ----
    {
        int t = tid >> 3;
        int s4 = (tid & 7)*4;
        int tl = t0 + t;
        float tmp[4] = {0,0,0,0};
        for (int j = 0; j <= tl; j++) {
            float p = Es[SS + j][t] * powa[tl - j];
            tmp[0] += p*ws[j][s4+0];
            tmp[1] += p*ws[j][s4+1];
            tmp[2] += p*ws[j][s4+2];
            tmp[3] += p*ws[j][s4+3];
        }
        float dec1 = powa[tl+1];
        #pragma unroll
        for (int i = 0; i < 4; i++)
            sc[t][s4+i] = RSCL * (dec1 * Es[s4+i][t] + ALPHA * tmp[i]);
    }
    __syncthreads();
    if (tid < 32) {
        float mx = -1e30f;
        for (int s = 0; s < SS; s++) mx = fmaxf(mx, sc[tid][s]);
        float sum = 0.f;
        for (int s = 0; s < SS; s++) { float e = expf(sc[tid][s]-mx); sc[tid][s] = e; sum += e; }
        float inv = 1.f/sum;
        for (int s = 0; s < SS; s++) sc[tid][s] *= inv;
    }
    __syncthreads();

    // ---- stage 3: coefficient matrix ----
    {
        int t = tid >> 3, s4 = (tid & 7)*4;
        float dec1 = powa[t0 + t + 1];
        #pragma unroll
        for (int i = 0; i < 4; i++) Cs[t][s4+i] = dec1 * sc[t][s4+i];
    }
    {
        int tq = tid >> 5;
        float bacc[4][4];
        #pragma unroll
        for (int i = 0; i < 4; i++)
            #pragma unroll
            for (int jj = 0; jj < 4; jj++) bacc[i][jj] = 0.f;
        for (int s = 0; s < SS; s++) {
            float at[4];
            #pragma unroll
            for (int i = 0; i < 4; i++) at[i] = sc[tq*4+i][s];
            #pragma unroll
            for (int jj = 0; jj < 4; jj++) {
                float wv = ws[lane + 32*jj][s];
                #pragma unroll
                for (int i = 0; i < 4; i++) bacc[i][jj] += at[i]*wv;
            }
        }
        #pragma unroll
        for (int i = 0; i < 4; i++)
            #pragma unroll
            for (int jj = 0; jj < 4; jj++) {
                int t = tq*4+i, j = lane + 32*jj, tl = t0 + t;
                Cs[t][SS + j] = (j <= tl) ? ALPHA * powa[tl - j] * bacc[i][jj] : 0.f;
            }
    }
    __syncthreads();

    // ---- stage 4: ctx = Cs @ [S_c ; V] with prefetch ----
    float4 rx4[4];
    auto fetch4 = [&](int it) {
        int d0 = (it / 5) * 128;
        int n0 = (it % 5) * 32;
        #pragma unroll
        for (int p = 0; p < 4; p++) {
            int f = tid + p*256;
            int r = f >> 5, dq = f & 31;
            int n = n0 + r;
            const float* src = (n < SS) ? &Scp[(size_t)n*DD + d0 + dq*4]
                                        : &vp[(size_t)(n-SS)*DD + d0 + dq*4];
            rx4[p] = *reinterpret_cast<const float4*>(src);
        }
    };

    fetch4(0);
    for (int dt = 0; dt < 8; dt++) {
        int d0 = dt*128;
        float4 acc4[4];
        #pragma unroll
        for (int i = 0; i < 4; i++) { acc4[i].x = 0.f; acc4[i].y = 0.f; acc4[i].z = 0.f; acc4[i].w = 0.f; }
        for (int nt = 0; nt < 5; nt++) {
            int it = dt*5 + nt;
            int n0 = nt*32;
            #pragma unroll
            for (int p = 0; p < 4; p++) {
                int f = tid + p*256;
                int r = f >> 5, dq = f & 31;
                *reinterpret_cast<float4*>(&Xs[r][dq*4]) = rx4[p];
            }
            __syncthreads();
            if (it + 1 < 40) fetch4(it + 1);
            #pragma unroll
            for (int k = 0; k < 32; k++) {
                float cv[4];
                #pragma unroll
                for (int i = 0; i < 4; i++) cv[i] = Cs[tg*4+i][n0+k];
                float4 xv = *reinterpret_cast<const float4*>(&Xs[k][lane*4]);
                #pragma unroll
                for (int i = 0; i < 4; i++) {
                    acc4[i].x += cv[i]*xv.x; acc4[i].y += cv[i]*xv.y;
                    acc4[i].z += cv[i]*xv.z; acc4[i].w += cv[i]*xv.w;
                }
            }
            __syncthreads();
        }
        #pragma unroll
        for (int i = 0; i < 4; i++) {
            size_t ro = (size_t)(b*TT + tc + t0 + tg*4 + i)*DD + d0 + lane*4;
            *reinterpret_cast<float4*>(&out[ro]) = acc4[i];
        }
    }
}

extern "C" void kernel_launch(void* const* d_in, const int* in_sizes, int n_in,
                              void* d_out, int out_size) {
    (void)in_sizes; (void)n_in; (void)out_size;
    const float* h      = (const float*)d_in[0];
    const float* state0 = (const float*)d_in[1];
    const float* gamma  = (const float*)d_in[2];
    const float* beta   = (const float*)d_in[3];
    const float* Wq     = (const float*)d_in[4];
    const float* bq     = (const float*)d_in[5];
    const float* Wv     = (const float*)d_in[6];
    const float* bv     = (const float*)d_in[7];
    float* out = (float*)d_out;

    static int configured = 0;
    if (!configured) {
        cudaFuncSetAttribute(k_proj_mma, cudaFuncAttributeMaxDynamicSharedMemorySize, PROJ_SMEM);
        configured = 1;
    }

    k_ln<<<BB*TT, 256>>>(h, gamma, beta);
    k_cvtw<<<(2*DD*DD/4)/256, 256>>>(Wq, Wv);

    dim3 gp(DD/128, (BB*TT)/128, 2);
    k_proj_mma<<<gp, 256, PROJ_SMEM>>>(bq, bv);

    dim3 gs((BB*TT)/64, 4);
    k_score1<<<gs, 256>>>(state0);
    k_softmax<<<(BB*TT)/128, 128>>>();

    dim3 gu(DD/128, BB*NCH);
    k_accum<<<gu, 256>>>();

    k_scan<<<(BB*SS*DD)/256, 256>>>(state0, out);

    dim3 gr(BB*NCH, CC/32);
    k_read<<<gr, 256>>>(out);
}